// round 1
// baseline (speedup 1.0000x reference)
#include <cuda_runtime.h>
#include <cstdint>

// ---------------- problem constants ----------------
#define C_CH   256
#define HH     224
#define HW     50176          // 224*224
#define LL     196            // 14*14
#define NPATCH 1024           // 4 * 16 * 16
#define SROW   38416          // 196*196
#define IMG_B  12845056       // 256*50176  (one batch image, also b-stride of x/out)

// ---------------- device scratch (no allocs allowed) ----------------
__device__ float g_Q [51380224];   // [n][c][l]  1024*256*196
__device__ float g_KL[12845056];   // low-res projected K: [b][c][hin][win] (max 112x112)
__device__ float g_VL[12845056];
__device__ float g_K [51380224];   // full-res, patch layout [n][c][l]
__device__ float g_V [51380224];
__device__ float g_S [39337984];   // [n][l][m]  1024*196*196

// ---------------- 8x8 microtile FMA step ----------------
__device__ __forceinline__ void mm_step(const float (*As)[128], const float (*Bs)[128],
                                        int r0, int c0, float acc[8][8]) {
#pragma unroll
  for (int kk = 0; kk < 8; kk++) {
    float a[8], b[8];
    *(float4*)&a[0] = *(const float4*)&As[kk][r0];
    *(float4*)&a[4] = *(const float4*)&As[kk][r0 + 4];
    *(float4*)&b[0] = *(const float4*)&Bs[kk][c0];
    *(float4*)&b[4] = *(const float4*)&Bs[kk][c0 + 4];
#pragma unroll
    for (int i = 0; i < 8; i++)
#pragma unroll
      for (int j = 0; j < 8; j++) acc[i][j] = fmaf(a[i], b[j], acc[i][j]);
  }
}

// ---------------- Q projection: out[n][o][l] = sum_c Wq[o][c] x[b,c,h,w] + bq[o] ----------------
// GEMM M=256(o) x N=200704(pixels) x K=256, tiles 128x128x8. 50176 % 128 == 0 -> no b crossing.
__global__ void __launch_bounds__(256) proj_q_kernel(
    const float* __restrict__ x, const float* __restrict__ Wm, const float* __restrict__ bias)
{
  __shared__ __align__(16) float As[8][128];
  __shared__ __align__(16) float Bs[8][128];
  const int tid = threadIdx.x;
  const int s0  = blockIdx.x * 128;
  const int o0  = blockIdx.y * 128;
  const int b   = s0 / HW;
  const int hw0 = s0 - b * HW;
  const float* xb = x + (size_t)b * IMG_B + hw0;

  const int wo = tid >> 1, wk = (tid & 1) * 4;
  const int xr = tid >> 5, xc = (tid & 31) * 4;
  const int r0 = (tid >> 4) * 8, c0 = (tid & 15) * 8;

  float acc[8][8];
#pragma unroll
  for (int i = 0; i < 8; i++)
#pragma unroll
    for (int j = 0; j < 8; j++) acc[i][j] = 0.f;

  for (int k0 = 0; k0 < 256; k0 += 8) {
    float4 wv = *(const float4*)&Wm[(o0 + wo) * 256 + k0 + wk];
    float4 xv = *(const float4*)&xb[(size_t)(k0 + xr) * HW + xc];
    As[wk + 0][wo] = wv.x; As[wk + 1][wo] = wv.y; As[wk + 2][wo] = wv.z; As[wk + 3][wo] = wv.w;
    *(float4*)&Bs[xr][xc] = xv;
    __syncthreads();
    mm_step(As, Bs, r0, c0, acc);
    __syncthreads();
  }

#pragma unroll
  for (int i = 0; i < 8; i++) {
    const int o = o0 + r0 + i;
    const float bo = bias[o];
#pragma unroll
    for (int j = 0; j < 8; j++) {
      const int hw = hw0 + c0 + j;
      const int h = hw / 224, w = hw % 224;
      const int n = (b << 8) + ((h / 14) << 4) + (w / 14);
      const int l = (h % 14) * 14 + (w % 14);
      g_Q[(size_t)n * HW + o * 196 + l] = acc[i][j] + bo;
    }
  }
}

// ---------------- low-res K/V projection (resize commutes with 1x1 conv) ----------------
// out[b][o][hw] = sum_c W[o][c] skip[b,c,hw] + bias[o].  hwin may not be /128 -> per-b tiles + guards.
__global__ void __launch_bounds__(256) proj_low_kernel(
    const float* __restrict__ x, const float* __restrict__ Wm, const float* __restrict__ bias,
    int hin, int tiles_per_b, int which)
{
  __shared__ __align__(16) float As[8][128];
  __shared__ __align__(16) float Bs[8][128];
  const int hwin = hin * hin;
  float* outp = which ? g_VL : g_KL;

  const int tid = threadIdx.x;
  const int b   = blockIdx.x / tiles_per_b;
  const int hw0 = (blockIdx.x - b * tiles_per_b) * 128;
  const int o0  = blockIdx.y * 128;
  const float* xb = x + (size_t)b * C_CH * hwin;

  const int wo = tid >> 1, wk = (tid & 1) * 4;
  const int xr = tid >> 5, xc = (tid & 31) * 4;
  const int r0 = (tid >> 4) * 8, c0 = (tid & 15) * 8;

  float acc[8][8];
#pragma unroll
  for (int i = 0; i < 8; i++)
#pragma unroll
    for (int j = 0; j < 8; j++) acc[i][j] = 0.f;

  for (int k0 = 0; k0 < 256; k0 += 8) {
    float4 wv = *(const float4*)&Wm[(o0 + wo) * 256 + k0 + wk];
    const float* xrow = xb + (size_t)(k0 + xr) * hwin;
    const int hw = hw0 + xc;
    float4 xv;
    if (hw + 3 < hwin) xv = *(const float4*)&xrow[hw];
    else {
      xv.x = (hw     < hwin) ? xrow[hw]     : 0.f;
      xv.y = (hw + 1 < hwin) ? xrow[hw + 1] : 0.f;
      xv.z = (hw + 2 < hwin) ? xrow[hw + 2] : 0.f;
      xv.w = 0.f;
    }
    As[wk + 0][wo] = wv.x; As[wk + 1][wo] = wv.y; As[wk + 2][wo] = wv.z; As[wk + 3][wo] = wv.w;
    *(float4*)&Bs[xr][xc] = xv;
    __syncthreads();
    mm_step(As, Bs, r0, c0, acc);
    __syncthreads();
  }

#pragma unroll
  for (int i = 0; i < 8; i++) {
    const int o = o0 + r0 + i;
    const float bo = bias[o];
    float* orow = outp + ((size_t)(b * C_CH + o)) * hwin + hw0 + c0;
#pragma unroll
    for (int j = 0; j < 8; j++) {
      if (hw0 + c0 + j < hwin) orow[j] = acc[i][j] + bo;
    }
  }
}

// ---------------- bilinear resize (half-pixel, edge clamp) into patch layout ----------------
__global__ void resize_kernel(int hin, int which)
{
  const float* in = which ? g_VL : g_KL;
  float* out      = which ? g_V  : g_K;
  const int t = blockIdx.x * 256 + threadIdx.x;   // < 51380224 exactly
  const int l  = t % 196;
  const int nc = t / 196;           // n*256 + c
  const int c  = nc & 255;
  const int n  = nc >> 8;
  const int b  = n >> 8;
  const int ph = (n >> 4) & 15, pw = n & 15;
  const int h = ph * 14 + l / 14;
  const int w = pw * 14 + l % 14;

  const float sc = (float)hin / 224.f;            // exact: 0.5 or 0.25
  const float sh = (h + 0.5f) * sc - 0.5f;
  const float sw = (w + 0.5f) * sc - 0.5f;
  const int ih = (int)floorf(sh), iw = (int)floorf(sw);
  const float fh = sh - (float)ih, fw = sw - (float)iw;
  const int h0 = max(ih, 0), h1 = min(ih + 1, hin - 1);
  const int w0 = max(iw, 0), w1 = min(iw + 1, hin - 1);

  const float* src = in + ((size_t)(b * C_CH + c)) * hin * hin;
  const float v00 = src[h0 * hin + w0], v01 = src[h0 * hin + w1];
  const float v10 = src[h1 * hin + w0], v11 = src[h1 * hin + w1];
  out[t] = (1.f - fh) * ((1.f - fw) * v00 + fw * v01)
         +        fh  * ((1.f - fw) * v10 + fw * v11);
}

// ---------------- S = Q^T K per patch: S[l][m] = sum_c Q[c][l] K[c][m] ----------------
__global__ void __launch_bounds__(256) attn_s_kernel()
{
  __shared__ __align__(16) float As[8][128];
  __shared__ __align__(16) float Bs[8][128];
  const int tid = threadIdx.x;
  const int n  = blockIdx.z;
  const int l0 = blockIdx.x * 128;
  const int m0 = blockIdx.y * 128;
  const float* Qn = g_Q + (size_t)n * HW;
  const float* Kn = g_K + (size_t)n * HW;
  const int lr = tid >> 5, lc = (tid & 31) * 4;
  const int r0 = (tid >> 4) * 8, c0 = (tid & 15) * 8;

  float acc[8][8];
#pragma unroll
  for (int i = 0; i < 8; i++)
#pragma unroll
    for (int j = 0; j < 8; j++) acc[i][j] = 0.f;

  for (int k0 = 0; k0 < 256; k0 += 8) {
    {
      const float* q = Qn + (k0 + lr) * 196;
      const int l = l0 + lc;
      if (l + 3 < 196) *(float4*)&As[lr][lc] = *(const float4*)&q[l];
      else {
#pragma unroll
        for (int j = 0; j < 4; j++) As[lr][lc + j] = (l + j < 196) ? q[l + j] : 0.f;
      }
    }
    {
      const float* kp = Kn + (k0 + lr) * 196;
      const int m = m0 + lc;
      if (m + 3 < 196) *(float4*)&Bs[lr][lc] = *(const float4*)&kp[m];
      else {
#pragma unroll
        for (int j = 0; j < 4; j++) Bs[lr][lc + j] = (m + j < 196) ? kp[m + j] : 0.f;
      }
    }
    __syncthreads();
    mm_step(As, Bs, r0, c0, acc);
    __syncthreads();
  }

  float* Sn = g_S + (size_t)n * SROW;
#pragma unroll
  for (int i = 0; i < 8; i++) {
    const int l = l0 + r0 + i;
    if (l < 196) {
#pragma unroll
      for (int j = 0; j < 8; j++) {
        const int m = m0 + c0 + j;
        if (m < 196) Sn[l * 196 + m] = acc[i][j];
      }
    }
  }
}

// ---------------- row softmax over m (warp per row) ----------------
__global__ void __launch_bounds__(256) softmax_kernel()
{
  const int row  = blockIdx.x * 8 + (threadIdx.x >> 5);
  const int lane = threadIdx.x & 31;
  float* p = g_S + (size_t)row * 196;
  float v[7];
  float mx = -1e30f;
#pragma unroll
  for (int t = 0; t < 7; t++) {
    const int idx = lane + t * 32;
    v[t] = (idx < 196) ? p[idx] : -1e30f;
    mx = fmaxf(mx, v[t]);
  }
#pragma unroll
  for (int off = 16; off > 0; off >>= 1) mx = fmaxf(mx, __shfl_xor_sync(0xffffffffu, mx, off));
  float sum = 0.f;
#pragma unroll
  for (int t = 0; t < 7; t++) {
    const int idx = lane + t * 32;
    v[t] = (idx < 196) ? __expf(v[t] - mx) : 0.f;
    sum += v[t];
  }
#pragma unroll
  for (int off = 16; off > 0; off >>= 1) sum += __shfl_xor_sync(0xffffffffu, sum, off);
  const float inv = 1.f / sum;
#pragma unroll
  for (int t = 0; t < 7; t++) {
    const int idx = lane + t * 32;
    if (idx < 196) p[idx] = v[t] * inv;
  }
}

// ---------------- O[c][l] = sum_m V[c][m] A[l][m]; write (or accumulate) unpatchified ----------------
__global__ void __launch_bounds__(256) attn_av_kernel(float* __restrict__ out, int accum)
{
  __shared__ __align__(16) float As[8][128];
  __shared__ __align__(16) float Bs[8][128];
  const int tid = threadIdx.x;
  const int n   = blockIdx.z;
  const int cT0 = blockIdx.y * 128;
  const int l0  = blockIdx.x * 128;
  const float* Vn = g_V + (size_t)n * HW;
  const float* Sn = g_S + (size_t)n * SROW;
  const int tr = tid >> 1, tk = (tid & 1) * 4;
  const int r0 = (tid >> 4) * 8, c0 = (tid & 15) * 8;

  float acc[8][8];
#pragma unroll
  for (int i = 0; i < 8; i++)
#pragma unroll
    for (int j = 0; j < 8; j++) acc[i][j] = 0.f;

  for (int m0 = 0; m0 < 196; m0 += 8) {
    {
      const int m = m0 + tk;
      const float* v = Vn + (cT0 + tr) * 196;
      float4 vv;
      if (m + 3 < 196) vv = *(const float4*)&v[m];
      else {
        vv.x = (m     < 196) ? v[m]     : 0.f;
        vv.y = (m + 1 < 196) ? v[m + 1] : 0.f;
        vv.z = (m + 2 < 196) ? v[m + 2] : 0.f;
        vv.w = 0.f;
      }
      As[tk + 0][tr] = vv.x; As[tk + 1][tr] = vv.y; As[tk + 2][tr] = vv.z; As[tk + 3][tr] = vv.w;
    }
    {
      const int l = l0 + tr;
      const int m = m0 + tk;
      float4 sv = make_float4(0.f, 0.f, 0.f, 0.f);
      if (l < 196) {
        const float* sr = Sn + l * 196;
        if (m + 3 < 196) sv = *(const float4*)&sr[m];
        else {
          sv.x = (m     < 196) ? sr[m]     : 0.f;
          sv.y = (m + 1 < 196) ? sr[m + 1] : 0.f;
          sv.z = (m + 2 < 196) ? sr[m + 2] : 0.f;
        }
      }
      Bs[tk + 0][tr] = sv.x; Bs[tk + 1][tr] = sv.y; Bs[tk + 2][tr] = sv.z; Bs[tk + 3][tr] = sv.w;
    }
    __syncthreads();
    mm_step(As, Bs, r0, c0, acc);
    __syncthreads();
  }

  const int b = n >> 8, ph = (n >> 4) & 15, pw = n & 15;
#pragma unroll
  for (int i = 0; i < 8; i++) {
    const int c = cT0 + r0 + i;
    float* oc = out + (size_t)b * IMG_B + (size_t)c * HW;
#pragma unroll
    for (int j = 0; j < 8; j++) {
      const int l = l0 + c0 + j;
      if (l < 196) {
        const int h = ph * 14 + l / 14;
        const int w = pw * 14 + l % 14;
        const size_t a = (size_t)h * 224 + w;
        if (accum) oc[a] += acc[i][j];
        else       oc[a]  = acc[i][j];
      }
    }
  }
}

// ---------------- launcher ----------------
extern "C" void kernel_launch(void* const* d_in, const int* in_sizes, int n_in,
                              void* d_out, int out_size) {
  const float* x     = (const float*)d_in[0];
  const float* skip0 = (const float*)d_in[1];
  const float* skip1 = (const float*)d_in[2];
  const float* Wq    = (const float*)d_in[3];
  const float* bq    = (const float*)d_in[4];
  const float* Wk    = (const float*)d_in[5];
  const float* bk    = (const float*)d_in[6];
  const float* Wv    = (const float*)d_in[7];
  const float* bv    = (const float*)d_in[8];
  float* out = (float*)d_out;

  (void)in_sizes; (void)n_in; (void)out_size;

  // Q projection (patch-layout output)
  proj_q_kernel<<<dim3(1568, 2), 256>>>(x, Wq, bq);

  for (int s = 0; s < 2; s++) {
    const float* skip = s ? skip1 : skip0;
    const int hin = s ? 56 : 112;
    const int hwin = hin * hin;
    const int tiles_per_b = (hwin + 127) / 128;
    dim3 gl(4 * tiles_per_b, 2);

    proj_low_kernel<<<gl, 256>>>(skip, Wk, bk, hin, tiles_per_b, 0);  // -> g_KL
    proj_low_kernel<<<gl, 256>>>(skip, Wv, bv, hin, tiles_per_b, 1);  // -> g_VL
    resize_kernel<<<200704, 256>>>(hin, 0);                            // g_KL -> g_K
    resize_kernel<<<200704, 256>>>(hin, 1);                            // g_VL -> g_V
    attn_s_kernel<<<dim3(2, 2, 1024), 256>>>();                        // S = Q^T K
    softmax_kernel<<<25088, 256>>>();                                  // row softmax
    attn_av_kernel<<<dim3(2, 2, 1024), 256>>>(out, s);                 // O = V A^T (+unpatchify)
  }
}

// round 2
// speedup vs baseline: 1.0048x; 1.0048x over previous
#include <cuda_runtime.h>
#include <cstdint>

// ---------------- problem constants ----------------
#define C_CH   256
#define HH     224
#define HW     50176          // 224*224
#define LL     196            // 14*14
#define NPATCH 1024           // 4 * 16 * 16
#define SROW   38416          // 196*196
#define IMG_B  12845056       // 256*50176  (one batch image, also b-stride of x/out)

// ---------------- device scratch (no allocs allowed) ----------------
__device__ float g_Q [51380224];   // [n][c][l]  1024*256*196
__device__ float g_KL[12845056];   // low-res projected K: [b][c][hin][win] (max 112x112)
__device__ float g_VL[12845056];
__device__ float g_K [51380224];   // full-res, patch layout [n][c][l]
__device__ float g_V [51380224];
__device__ float g_S [39337984];   // [n][l][m]  1024*196*196

// ---------------- 8x8 microtile FMA step ----------------
__device__ __forceinline__ void mm_step(const float (*As)[128], const float (*Bs)[128],
                                        int r0, int c0, float acc[8][8]) {
#pragma unroll
  for (int kk = 0; kk < 8; kk++) {
    float a[8], b[8];
    *(float4*)&a[0] = *(const float4*)&As[kk][r0];
    *(float4*)&a[4] = *(const float4*)&As[kk][r0 + 4];
    *(float4*)&b[0] = *(const float4*)&Bs[kk][c0];
    *(float4*)&b[4] = *(const float4*)&Bs[kk][c0 + 4];
#pragma unroll
    for (int i = 0; i < 8; i++)
#pragma unroll
      for (int j = 0; j < 8; j++) acc[i][j] = fmaf(a[i], b[j], acc[i][j]);
  }
}

// ---------------- Q projection: out[n][o][l] = sum_c Wq[o][c] x[b,c,h,w] + bq[o] ----------------
// GEMM M=256(o) x N=200704(pixels) x K=256, tiles 128x128x8. 50176 % 128 == 0 -> no b crossing.
__global__ void __launch_bounds__(256) proj_q_kernel(
    const float* __restrict__ x, const float* __restrict__ Wm, const float* __restrict__ bias)
{
  __shared__ __align__(16) float As[8][128];
  __shared__ __align__(16) float Bs[8][128];
  const int tid = threadIdx.x;
  const int s0  = blockIdx.x * 128;
  const int o0  = blockIdx.y * 128;
  const int b   = s0 / HW;
  const int hw0 = s0 - b * HW;
  const float* xb = x + (size_t)b * IMG_B + hw0;

  const int wo = tid >> 1, wk = (tid & 1) * 4;
  const int xr = tid >> 5, xc = (tid & 31) * 4;
  const int r0 = (tid >> 4) * 8, c0 = (tid & 15) * 8;

  float acc[8][8];
#pragma unroll
  for (int i = 0; i < 8; i++)
#pragma unroll
    for (int j = 0; j < 8; j++) acc[i][j] = 0.f;

  for (int k0 = 0; k0 < 256; k0 += 8) {
    float4 wv = *(const float4*)&Wm[(o0 + wo) * 256 + k0 + wk];
    float4 xv = *(const float4*)&xb[(size_t)(k0 + xr) * HW + xc];
    As[wk + 0][wo] = wv.x; As[wk + 1][wo] = wv.y; As[wk + 2][wo] = wv.z; As[wk + 3][wo] = wv.w;
    *(float4*)&Bs[xr][xc] = xv;
    __syncthreads();
    mm_step(As, Bs, r0, c0, acc);
    __syncthreads();
  }

#pragma unroll
  for (int i = 0; i < 8; i++) {
    const int o = o0 + r0 + i;
    const float bo = bias[o];
#pragma unroll
    for (int j = 0; j < 8; j++) {
      const int hw = hw0 + c0 + j;
      const int h = hw / 224, w = hw % 224;
      const int n = (b << 8) + ((h / 14) << 4) + (w / 14);
      const int l = (h % 14) * 14 + (w % 14);
      g_Q[(size_t)n * HW + o * 196 + l] = acc[i][j] + bo;
    }
  }
}

// ---------------- low-res K/V projection (resize commutes with 1x1 conv) ----------------
// out[b][o][hw] = sum_c W[o][c] skip[b,c,hw] + bias[o].  hwin may not be /128 -> per-b tiles + guards.
__global__ void __launch_bounds__(256) proj_low_kernel(
    const float* __restrict__ x, const float* __restrict__ Wm, const float* __restrict__ bias,
    int hin, int tiles_per_b, int which)
{
  __shared__ __align__(16) float As[8][128];
  __shared__ __align__(16) float Bs[8][128];
  const int hwin = hin * hin;
  float* outp = which ? g_VL : g_KL;

  const int tid = threadIdx.x;
  const int b   = blockIdx.x / tiles_per_b;
  const int hw0 = (blockIdx.x - b * tiles_per_b) * 128;
  const int o0  = blockIdx.y * 128;
  const float* xb = x + (size_t)b * C_CH * hwin;

  const int wo = tid >> 1, wk = (tid & 1) * 4;
  const int xr = tid >> 5, xc = (tid & 31) * 4;
  const int r0 = (tid >> 4) * 8, c0 = (tid & 15) * 8;

  float acc[8][8];
#pragma unroll
  for (int i = 0; i < 8; i++)
#pragma unroll
    for (int j = 0; j < 8; j++) acc[i][j] = 0.f;

  for (int k0 = 0; k0 < 256; k0 += 8) {
    float4 wv = *(const float4*)&Wm[(o0 + wo) * 256 + k0 + wk];
    const float* xrow = xb + (size_t)(k0 + xr) * hwin;
    const int hw = hw0 + xc;
    float4 xv;
    if (hw + 3 < hwin) xv = *(const float4*)&xrow[hw];
    else {
      xv.x = (hw     < hwin) ? xrow[hw]     : 0.f;
      xv.y = (hw + 1 < hwin) ? xrow[hw + 1] : 0.f;
      xv.z = (hw + 2 < hwin) ? xrow[hw + 2] : 0.f;
      xv.w = 0.f;
    }
    As[wk + 0][wo] = wv.x; As[wk + 1][wo] = wv.y; As[wk + 2][wo] = wv.z; As[wk + 3][wo] = wv.w;
    *(float4*)&Bs[xr][xc] = xv;
    __syncthreads();
    mm_step(As, Bs, r0, c0, acc);
    __syncthreads();
  }

#pragma unroll
  for (int i = 0; i < 8; i++) {
    const int o = o0 + r0 + i;
    const float bo = bias[o];
    float* orow = outp + ((size_t)(b * C_CH + o)) * hwin + hw0 + c0;
#pragma unroll
    for (int j = 0; j < 8; j++) {
      if (hw0 + c0 + j < hwin) orow[j] = acc[i][j] + bo;
    }
  }
}

// ---------------- bilinear resize (half-pixel, edge clamp) into patch layout ----------------
__global__ void resize_kernel(int hin, int which)
{
  const float* in = which ? g_VL : g_KL;
  float* out      = which ? g_V  : g_K;
  const int t = blockIdx.x * 256 + threadIdx.x;   // < 51380224 exactly
  const int l  = t % 196;
  const int nc = t / 196;           // n*256 + c
  const int c  = nc & 255;
  const int n  = nc >> 8;
  const int b  = n >> 8;
  const int ph = (n >> 4) & 15, pw = n & 15;
  const int h = ph * 14 + l / 14;
  const int w = pw * 14 + l % 14;

  const float sc = (float)hin / 224.f;            // exact: 0.5 or 0.25
  const float sh = (h + 0.5f) * sc - 0.5f;
  const float sw = (w + 0.5f) * sc - 0.5f;
  const int ih = (int)floorf(sh), iw = (int)floorf(sw);
  const float fh = sh - (float)ih, fw = sw - (float)iw;
  const int h0 = max(ih, 0), h1 = min(ih + 1, hin - 1);
  const int w0 = max(iw, 0), w1 = min(iw + 1, hin - 1);

  const float* src = in + ((size_t)(b * C_CH + c)) * hin * hin;
  const float v00 = src[h0 * hin + w0], v01 = src[h0 * hin + w1];
  const float v10 = src[h1 * hin + w0], v11 = src[h1 * hin + w1];
  out[t] = (1.f - fh) * ((1.f - fw) * v00 + fw * v01)
         +        fh  * ((1.f - fw) * v10 + fw * v11);
}

// ---------------- S = Q^T K per patch: S[l][m] = sum_c Q[c][l] K[c][m] ----------------
__global__ void __launch_bounds__(256) attn_s_kernel()
{
  __shared__ __align__(16) float As[8][128];
  __shared__ __align__(16) float Bs[8][128];
  const int tid = threadIdx.x;
  const int n  = blockIdx.z;
  const int l0 = blockIdx.x * 128;
  const int m0 = blockIdx.y * 128;
  const float* Qn = g_Q + (size_t)n * HW;
  const float* Kn = g_K + (size_t)n * HW;
  const int lr = tid >> 5, lc = (tid & 31) * 4;
  const int r0 = (tid >> 4) * 8, c0 = (tid & 15) * 8;

  float acc[8][8];
#pragma unroll
  for (int i = 0; i < 8; i++)
#pragma unroll
    for (int j = 0; j < 8; j++) acc[i][j] = 0.f;

  for (int k0 = 0; k0 < 256; k0 += 8) {
    {
      const float* q = Qn + (k0 + lr) * 196;
      const int l = l0 + lc;
      if (l + 3 < 196) *(float4*)&As[lr][lc] = *(const float4*)&q[l];
      else {
#pragma unroll
        for (int j = 0; j < 4; j++) As[lr][lc + j] = (l + j < 196) ? q[l + j] : 0.f;
      }
    }
    {
      const float* kp = Kn + (k0 + lr) * 196;
      const int m = m0 + lc;
      if (m + 3 < 196) *(float4*)&Bs[lr][lc] = *(const float4*)&kp[m];
      else {
#pragma unroll
        for (int j = 0; j < 4; j++) Bs[lr][lc + j] = (m + j < 196) ? kp[m + j] : 0.f;
      }
    }
    __syncthreads();
    mm_step(As, Bs, r0, c0, acc);
    __syncthreads();
  }

  float* Sn = g_S + (size_t)n * SROW;
#pragma unroll
  for (int i = 0; i < 8; i++) {
    const int l = l0 + r0 + i;
    if (l < 196) {
#pragma unroll
      for (int j = 0; j < 8; j++) {
        const int m = m0 + c0 + j;
        if (m < 196) Sn[l * 196 + m] = acc[i][j];
      }
    }
  }
}

// ---------------- row softmax over m (warp per row) ----------------
__global__ void __launch_bounds__(256) softmax_kernel()
{
  const int row  = blockIdx.x * 8 + (threadIdx.x >> 5);
  const int lane = threadIdx.x & 31;
  float* p = g_S + (size_t)row * 196;
  float v[7];
  float mx = -1e30f;
#pragma unroll
  for (int t = 0; t < 7; t++) {
    const int idx = lane + t * 32;
    v[t] = (idx < 196) ? p[idx] : -1e30f;
    mx = fmaxf(mx, v[t]);
  }
#pragma unroll
  for (int off = 16; off > 0; off >>= 1) mx = fmaxf(mx, __shfl_xor_sync(0xffffffffu, mx, off));
  float sum = 0.f;
#pragma unroll
  for (int t = 0; t < 7; t++) {
    const int idx = lane + t * 32;
    v[t] = (idx < 196) ? __expf(v[t] - mx) : 0.f;
    sum += v[t];
  }
#pragma unroll
  for (int off = 16; off > 0; off >>= 1) sum += __shfl_xor_sync(0xffffffffu, sum, off);
  const float inv = 1.f / sum;
#pragma unroll
  for (int t = 0; t < 7; t++) {
    const int idx = lane + t * 32;
    if (idx < 196) p[idx] = v[t] * inv;
  }
}

// ---------------- O[c][l] = sum_m V[c][m] A[l][m]; write (or accumulate) unpatchified ----------------
__global__ void __launch_bounds__(256) attn_av_kernel(float* __restrict__ out, int accum)
{
  __shared__ __align__(16) float As[8][128];
  __shared__ __align__(16) float Bs[8][128];
  const int tid = threadIdx.x;
  const int n   = blockIdx.z;
  const int cT0 = blockIdx.y * 128;
  const int l0  = blockIdx.x * 128;
  const float* Vn = g_V + (size_t)n * HW;
  const float* Sn = g_S + (size_t)n * SROW;
  const int tr = tid >> 1, tk = (tid & 1) * 4;
  const int r0 = (tid >> 4) * 8, c0 = (tid & 15) * 8;

  float acc[8][8];
#pragma unroll
  for (int i = 0; i < 8; i++)
#pragma unroll
    for (int j = 0; j < 8; j++) acc[i][j] = 0.f;

  for (int m0 = 0; m0 < 196; m0 += 8) {
    {
      const int m = m0 + tk;
      const float* v = Vn + (cT0 + tr) * 196;
      float4 vv;
      if (m + 3 < 196) vv = *(const float4*)&v[m];
      else {
        vv.x = (m     < 196) ? v[m]     : 0.f;
        vv.y = (m + 1 < 196) ? v[m + 1] : 0.f;
        vv.z = (m + 2 < 196) ? v[m + 2] : 0.f;
        vv.w = 0.f;
      }
      As[tk + 0][tr] = vv.x; As[tk + 1][tr] = vv.y; As[tk + 2][tr] = vv.z; As[tk + 3][tr] = vv.w;
    }
    {
      const int l = l0 + tr;
      const int m = m0 + tk;
      float4 sv = make_float4(0.f, 0.f, 0.f, 0.f);
      if (l < 196) {
        const float* sr = Sn + l * 196;
        if (m + 3 < 196) sv = *(const float4*)&sr[m];
        else {
          sv.x = (m     < 196) ? sr[m]     : 0.f;
          sv.y = (m + 1 < 196) ? sr[m + 1] : 0.f;
          sv.z = (m + 2 < 196) ? sr[m + 2] : 0.f;
        }
      }
      Bs[tk + 0][tr] = sv.x; Bs[tk + 1][tr] = sv.y; Bs[tk + 2][tr] = sv.z; Bs[tk + 3][tr] = sv.w;
    }
    __syncthreads();
    mm_step(As, Bs, r0, c0, acc);
    __syncthreads();
  }

  const int b = n >> 8, ph = (n >> 4) & 15, pw = n & 15;
#pragma unroll
  for (int i = 0; i < 8; i++) {
    const int c = cT0 + r0 + i;
    float* oc = out + (size_t)b * IMG_B + (size_t)c * HW;
#pragma unroll
    for (int j = 0; j < 8; j++) {
      const int l = l0 + c0 + j;
      if (l < 196) {
        const int h = ph * 14 + l / 14;
        const int w = pw * 14 + l % 14;
        const size_t a = (size_t)h * 224 + w;
        if (accum) oc[a] += acc[i][j];
        else       oc[a]  = acc[i][j];
      }
    }
  }
}

// ---------------- launcher ----------------
extern "C" void kernel_launch(void* const* d_in, const int* in_sizes, int n_in,
                              void* d_out, int out_size) {
  const float* x     = (const float*)d_in[0];
  const float* skip0 = (const float*)d_in[1];
  const float* skip1 = (const float*)d_in[2];
  const float* Wq    = (const float*)d_in[3];
  const float* bq    = (const float*)d_in[4];
  const float* Wk    = (const float*)d_in[5];
  const float* bk    = (const float*)d_in[6];
  const float* Wv    = (const float*)d_in[7];
  const float* bv    = (const float*)d_in[8];
  float* out = (float*)d_out;

  (void)in_sizes; (void)n_in; (void)out_size;

  // Q projection (patch-layout output)
  proj_q_kernel<<<dim3(1568, 2), 256>>>(x, Wq, bq);

  for (int s = 0; s < 2; s++) {
    const float* skip = s ? skip1 : skip0;
    const int hin = s ? 56 : 112;
    const int hwin = hin * hin;
    const int tiles_per_b = (hwin + 127) / 128;
    dim3 gl(4 * tiles_per_b, 2);

    proj_low_kernel<<<gl, 256>>>(skip, Wk, bk, hin, tiles_per_b, 0);  // -> g_KL
    proj_low_kernel<<<gl, 256>>>(skip, Wv, bv, hin, tiles_per_b, 1);  // -> g_VL
    resize_kernel<<<200704, 256>>>(hin, 0);                            // g_KL -> g_K
    resize_kernel<<<200704, 256>>>(hin, 1);                            // g_VL -> g_V
    attn_s_kernel<<<dim3(2, 2, 1024), 256>>>();                        // S = Q^T K
    softmax_kernel<<<25088, 256>>>();                                  // row softmax
    attn_av_kernel<<<dim3(2, 2, 1024), 256>>>(out, s);                 // O = V A^T (+unpatchify)
  }
}

// round 3
// speedup vs baseline: 1.7658x; 1.7573x over previous
#include <cuda_runtime.h>
#include <cuda_bf16.h>
#include <cstdint>

#define HWF   50176            // 224*224
#define QSZ   50176            // 196*256 per-patch Q/K/V size
#define PSZ   38416            // 196*196
#define NQ    51380224ULL      // 1024*196*256
#define NP    39337984ULL      // 1024*196*196
#define IMG_B 12845056         // 256*50176

// ---------------- device scratch ----------------
__device__ float g_Q [51380224];      // [n][l][c]
__device__ float g_K [102760448];     // [s][n][m][c]
__device__ float g_Vt[102760448];     // [s][n][c][m]
__device__ float g_S [78675968];      // [s][n][l][m]  (S then P in place)
__device__ float g_KL[12845056];      // lowres [b][hw][c]
__device__ float g_VL[12845056];

// ---------------- helpers ----------------
__device__ __forceinline__ void split_f32(float v, unsigned short& h, unsigned short& l) {
  __nv_bfloat16 bh = __float2bfloat16(v);
  h = __bfloat16_as_ushort(bh);
  l = __bfloat16_as_ushort(__float2bfloat16(v - __bfloat162float(bh)));
}
__device__ __forceinline__ unsigned pack2(float a, float b) {
  unsigned short h0, l0, h1, l1; split_f32(a, h0, l0); split_f32(b, h1, l1);
  (void)l0; (void)l1;
  return (unsigned)h0 | ((unsigned)h1 << 16);
}
__device__ __forceinline__ void mma_bf16(float d[4], const unsigned a[4], const unsigned b[2]) {
  asm volatile("mma.sync.aligned.m16n8k16.row.col.f32.bf16.bf16.f32 "
               "{%0,%1,%2,%3}, {%4,%5,%6,%7}, {%8,%9}, {%0,%1,%2,%3};\n"
               : "+f"(d[0]), "+f"(d[1]), "+f"(d[2]), "+f"(d[3])
               : "r"(a[0]), "r"(a[1]), "r"(a[2]), "r"(a[3]), "r"(b[0]), "r"(b[1]));
}
#define LDSM4(r, addr) \
  asm volatile("ldmatrix.sync.aligned.m8n8.x4.shared.b16 {%0,%1,%2,%3},[%4];" \
               : "=r"(r[0]), "=r"(r[1]), "=r"(r[2]), "=r"(r[3]) : "r"(addr))

__device__ __forceinline__ void bilin(int n, int l, int hin,
                                      int& i00, int& i01, int& i10, int& i11,
                                      float& fh, float& fw) {
  const int ph = (n >> 4) & 15, pw = n & 15;
  const int h = ph * 14 + l / 14;
  const int w = pw * 14 + l % 14;
  const float sc = (float)hin / 224.f;
  const float sh = (h + 0.5f) * sc - 0.5f;
  const float sw = (w + 0.5f) * sc - 0.5f;
  const int ih = (int)floorf(sh), iw = (int)floorf(sw);
  fh = sh - (float)ih; fw = sw - (float)iw;
  const int h0 = max(ih, 0), h1 = min(ih + 1, hin - 1);
  const int w0 = max(iw, 0), w1 = min(iw + 1, hin - 1);
  i00 = h0 * hin + w0; i01 = h0 * hin + w1; i10 = h1 * hin + w0; i11 = h1 * hin + w1;
}

// ==================================================================
// Generic bf16x3 tile GEMM.  BM=112 (7 warps x m16), K-chunk 32.
// MODE 0: Q proj   A=x[b][c][hw] (transposed stage)  B=Wq  -> g_Q [n][l][c]
// MODE 1: low proj A=skip                             B=W   -> g_KL/g_VL [b][hw][c]
// MODE 2: S = Q K^T per patch (BN=112)                      -> g_S[s]
// MODE 3: O = P V^T fused over 2 skips (K=416)              -> d_out (unpatchified)
// ==================================================================
template<int MODE>
__global__ void __launch_bounds__(224, 2) mm_kernel(
    const float* __restrict__ Ap, const float* __restrict__ Bp,
    const float* __restrict__ bias, float* __restrict__ outp,
    int hwin, int s, int which)
{
  constexpr int NF  = (MODE == 2) ? 14 : 16;
  constexpr int NCH = (MODE == 3) ? 13 : 8;
  __shared__ __align__(16) unsigned char smem[38400];
  unsigned short* Ah = (unsigned short*)smem;            // [112][40]
  unsigned short* Al = (unsigned short*)(smem + 8960);
  unsigned short* Bh = (unsigned short*)(smem + 17920);  // [128][40]
  unsigned short* Bl = (unsigned short*)(smem + 28160);

  const int tid = threadIdx.x, warp = tid >> 5, lane = tid & 31;
  const int qr = lane >> 2, kc2 = (lane & 3) * 2;
  const int t8 = lane >> 3, l7 = lane & 7;
  const int n = blockIdx.z;

  const unsigned sbase  = (unsigned)__cvta_generic_to_shared(smem);
  const unsigned a_addr = sbase + ((warp * 16 + l7 + (t8 & 1) * 8) * 40 + (t8 >> 1) * 8) * 2;
  const unsigned b_addr = sbase + 17920 + ((l7 + (t8 >> 1) * 8) * 40 + (t8 & 1) * 8) * 2;

  float acc[NF][4];
#pragma unroll
  for (int i = 0; i < NF; i++) { acc[i][0] = acc[i][1] = acc[i][2] = acc[i][3] = 0.f; }

#pragma unroll 1
  for (int ch = 0; ch < NCH; ch++) {
    const int k0 = ch * 32;
    // ---------------- stage A ----------------
    if (MODE <= 1) {
      const int p0 = blockIdx.x * 112;
      const int b = p0 / hwin;
      const float* xb = Ap + (size_t)b * 256 * hwin + (p0 - b * hwin);
      for (int idx = tid; idx < 32 * 112; idx += 224) {
        const int kk = idx / 112, p = idx - kk * 112;
        unsigned short h, l; split_f32(xb[(size_t)(k0 + kk) * hwin + p], h, l);
        Ah[p * 40 + kk] = h; Al[p * 40 + kk] = l;
      }
    } else if (MODE == 2) {
      const float* An = g_Q + (size_t)n * QSZ;
      const int Lb = blockIdx.x * 112;
      for (int idx = tid; idx < 112 * 16; idx += 224) {
        const int r = idx >> 4, cc = (idx & 15) * 2;
        const int l = Lb + r;
        float2 v = make_float2(0.f, 0.f);
        if (l < 196) v = *(const float2*)&An[l * 256 + k0 + cc];
        unsigned short h0, l0, h1, l1; split_f32(v.x, h0, l0); split_f32(v.y, h1, l1);
        *(unsigned*)&Ah[r * 40 + cc] = (unsigned)h0 | ((unsigned)h1 << 16);
        *(unsigned*)&Al[r * 40 + cc] = (unsigned)l0 | ((unsigned)l1 << 16);
      }
    } else {
      const int Lb = blockIdx.x * 112;
      for (int idx = tid; idx < 112 * 32; idx += 224) {
        const int r = idx >> 5, kk = idx & 31;
        const int l = Lb + r, gk = k0 + kk;
        float v = 0.f;
        if (l < 196 && gk < 392) {
          const int ss = (gk >= 196) ? 1 : 0;
          const int m = gk - ss * 196;
          v = g_S[(size_t)ss * NP + (size_t)n * PSZ + l * 196 + m];
        }
        unsigned short h, lo; split_f32(v, h, lo);
        Ah[r * 40 + kk] = h; Al[r * 40 + kk] = lo;
      }
    }
    // ---------------- stage B ----------------
    if (MODE <= 1) {
      const int o0 = blockIdx.y * 128;
      for (int idx = tid; idx < 128 * 16; idx += 224) {
        const int r = idx >> 4, cc = (idx & 15) * 2;
        float2 v = *(const float2*)&Bp[(o0 + r) * 256 + k0 + cc];
        unsigned short h0, l0, h1, l1; split_f32(v.x, h0, l0); split_f32(v.y, h1, l1);
        *(unsigned*)&Bh[r * 40 + cc] = (unsigned)h0 | ((unsigned)h1 << 16);
        *(unsigned*)&Bl[r * 40 + cc] = (unsigned)l0 | ((unsigned)l1 << 16);
      }
    } else if (MODE == 2) {
      const float* Kn = g_K + (size_t)s * NQ + (size_t)n * QSZ;
      const int Mb = blockIdx.y * 112;
      for (int idx = tid; idx < 112 * 16; idx += 224) {
        const int r = idx >> 4, cc = (idx & 15) * 2;
        const int m = Mb + r;
        float2 v = make_float2(0.f, 0.f);
        if (m < 196) v = *(const float2*)&Kn[m * 256 + k0 + cc];
        unsigned short h0, l0, h1, l1; split_f32(v.x, h0, l0); split_f32(v.y, h1, l1);
        *(unsigned*)&Bh[r * 40 + cc] = (unsigned)h0 | ((unsigned)h1 << 16);
        *(unsigned*)&Bl[r * 40 + cc] = (unsigned)l0 | ((unsigned)l1 << 16);
      }
    } else {
      const int c0 = blockIdx.y * 128;
      for (int idx = tid; idx < 128 * 32; idx += 224) {
        const int r = idx >> 5, kk = idx & 31;
        const int gk = k0 + kk;
        float v = 0.f;
        if (gk < 392) {
          const int ss = (gk >= 196) ? 1 : 0;
          const int m = gk - ss * 196;
          v = g_Vt[(size_t)ss * NQ + (size_t)n * QSZ + (c0 + r) * 196 + m];
        }
        unsigned short h, lo; split_f32(v, h, lo);
        Bh[r * 40 + kk] = h; Bl[r * 40 + kk] = lo;
      }
    }
    __syncthreads();
    // ---------------- MMA ----------------
#pragma unroll
    for (int kk = 0; kk < 2; kk++) {
      unsigned ah[4], al[4];
      LDSM4(ah, a_addr + kk * 32);
      LDSM4(al, a_addr + 8960 + kk * 32);
#pragma unroll
      for (int nf = 0; nf < NF; nf += 2) {
        unsigned bh[4], bl[4];
        LDSM4(bh, b_addr + nf * 640 + kk * 32);
        LDSM4(bl, b_addr + 10240 + nf * 640 + kk * 32);
        mma_bf16(acc[nf], ah, bh);     mma_bf16(acc[nf + 1], ah, bh + 2);
        mma_bf16(acc[nf], al, bh);     mma_bf16(acc[nf + 1], al, bh + 2);
        mma_bf16(acc[nf], ah, bl);     mma_bf16(acc[nf + 1], ah, bl + 2);
      }
    }
    __syncthreads();
  }

  // ---------------- epilogues ----------------
  if (MODE == 0) {
    const int p0 = blockIdx.x * 112, o0 = blockIdx.y * 128;
    const int b = p0 / hwin;
#pragma unroll
    for (int half = 0; half < 2; half++) {
      const int p = p0 + warp * 16 + qr + half * 8;
      const int pl = p - b * hwin;
      const int h = pl / 224, w = pl - (pl / 224) * 224;
      const int nn = (b << 8) + (h / 14) * 16 + (w / 14);
      const int l = (h % 14) * 14 + (w % 14);
      float* dst = g_Q + (size_t)nn * QSZ + l * 256;
#pragma unroll
      for (int nf = 0; nf < NF; nf++) {
        const int o = o0 + nf * 8 + kc2;
        float2 v = make_float2(acc[nf][half * 2] + bias[o], acc[nf][half * 2 + 1] + bias[o + 1]);
        *(float2*)&dst[o] = v;
      }
    }
  } else if (MODE == 1) {
    const int p0 = blockIdx.x * 112, o0 = blockIdx.y * 128;
    const int b = p0 / hwin;
    float* outF = which ? g_VL : g_KL;
#pragma unroll
    for (int half = 0; half < 2; half++) {
      const int p = p0 + warp * 16 + qr + half * 8;
      float* dst = outF + (size_t)p * 256;   // p already == b*hwin + pl
#pragma unroll
      for (int nf = 0; nf < NF; nf++) {
        const int o = o0 + nf * 8 + kc2;
        float2 v = make_float2(acc[nf][half * 2] + bias[o], acc[nf][half * 2 + 1] + bias[o + 1]);
        *(float2*)&dst[o] = v;
      }
    }
  } else if (MODE == 2) {
    float* Sn = g_S + (size_t)s * NP + (size_t)n * PSZ;
    const int Lb = blockIdx.x * 112, Mb = blockIdx.y * 112;
#pragma unroll
    for (int half = 0; half < 2; half++) {
      const int l = Lb + warp * 16 + qr + half * 8;
      if (l < 196) {
#pragma unroll
        for (int nf = 0; nf < NF; nf++) {
          const int m = Mb + nf * 8 + kc2;
          if (m < 196)
            *(float2*)&Sn[l * 196 + m] = make_float2(acc[nf][half * 2], acc[nf][half * 2 + 1]);
        }
      }
    }
  } else {
    float* T = (float*)smem;   // [64][133]
    const int Lb = blockIdx.x * 112, c0 = blockIdx.y * 128;
    const int b = n >> 8, php = (n >> 4) & 15, pwp = n & 15;
#pragma unroll 1
    for (int pass = 0; pass < 2; pass++) {
      __syncthreads();
      if ((warp >> 2) == pass) {
        const int lr = warp * 16 + qr - pass * 64;
#pragma unroll
        for (int nf = 0; nf < NF; nf++) {
          const int c = nf * 8 + kc2;
          T[lr * 133 + c]           = acc[nf][0];
          T[lr * 133 + c + 1]       = acc[nf][1];
          T[(lr + 8) * 133 + c]     = acc[nf][2];
          T[(lr + 8) * 133 + c + 1] = acc[nf][3];
        }
      }
      __syncthreads();
      const int nrows = pass ? 48 : 64;
      for (int idx = tid; idx < 128 * 64; idx += 224) {
        const int c = idx >> 6, lr = idx & 63;
        const int l = Lb + pass * 64 + lr;
        if (lr < nrows && l < 196) {
          const int hh = php * 14 + l / 14, ww = pwp * 14 + l % 14;
          outp[(size_t)b * IMG_B + (size_t)(c0 + c) * HWF + hh * 224 + ww] = T[lr * 133 + c];
        }
      }
    }
  }
}

// ---------------- resize K: g_KL [b][hw][c] -> g_K [s][n][m][c] ----------------
__global__ void resizeK_kernel(int hin, int s)
{
  const int r = blockIdx.x;               // n*196 + m
  const int nn = r / 196, m = r - nn * 196;
  const int c = threadIdx.x;
  const int b = nn >> 8;
  int i00, i01, i10, i11; float fh, fw;
  bilin(nn, m, hin, i00, i01, i10, i11, fh, fw);
  const size_t bb = (size_t)b * hin * hin * 256;
  const float v00 = g_KL[bb + (size_t)i00 * 256 + c], v01 = g_KL[bb + (size_t)i01 * 256 + c];
  const float v10 = g_KL[bb + (size_t)i10 * 256 + c], v11 = g_KL[bb + (size_t)i11 * 256 + c];
  g_K[(size_t)s * NQ + (size_t)nn * QSZ + m * 256 + c] =
      (1.f - fh) * ((1.f - fw) * v00 + fw * v01) + fh * ((1.f - fw) * v10 + fw * v11);
}

// ---------------- resize V + transpose: g_VL [b][hw][c] -> g_Vt [s][n][c][m] ----------------
__global__ void resizeV_kernel(int hin, int s)
{
  __shared__ float sm[28 * 257];
  const int mt = blockIdx.x, nn = blockIdx.y;
  const int c = threadIdx.x;
  const int b = nn >> 8;
  const size_t bb = (size_t)b * hin * hin * 256;
#pragma unroll 1
  for (int li = 0; li < 28; li++) {
    int i00, i01, i10, i11; float fh, fw;
    bilin(nn, mt * 28 + li, hin, i00, i01, i10, i11, fh, fw);
    const float v00 = g_VL[bb + (size_t)i00 * 256 + c], v01 = g_VL[bb + (size_t)i01 * 256 + c];
    const float v10 = g_VL[bb + (size_t)i10 * 256 + c], v11 = g_VL[bb + (size_t)i11 * 256 + c];
    sm[li * 257 + c] = (1.f - fh) * ((1.f - fw) * v00 + fw * v01)
                     + fh * ((1.f - fw) * v10 + fw * v11);
  }
  __syncthreads();
  float* dst = g_Vt + (size_t)s * NQ + (size_t)nn * QSZ;
  for (int idx = c; idx < 28 * 256; idx += 256) {
    const int cc = idx / 28, li = idx - cc * 28;
    dst[cc * 196 + mt * 28 + li] = sm[li * 257 + cc];
  }
}

// ---------------- row softmax in place on g_S[s] ----------------
__global__ void __launch_bounds__(256) softmax_kernel(int s)
{
  const int row  = blockIdx.x * 8 + (threadIdx.x >> 5);   // < 200704
  const int lane = threadIdx.x & 31;
  float* p = g_S + (size_t)s * NP + (size_t)row * 196;
  float v[7];
  float mx = -1e30f;
#pragma unroll
  for (int t = 0; t < 7; t++) {
    const int idx = lane + t * 32;
    v[t] = (idx < 196) ? p[idx] : -1e30f;
    mx = fmaxf(mx, v[t]);
  }
#pragma unroll
  for (int off = 16; off > 0; off >>= 1) mx = fmaxf(mx, __shfl_xor_sync(0xffffffffu, mx, off));
  float sum = 0.f;
#pragma unroll
  for (int t = 0; t < 7; t++) {
    const int idx = lane + t * 32;
    v[t] = (idx < 196) ? __expf(v[t] - mx) : 0.f;
    sum += v[t];
  }
#pragma unroll
  for (int off = 16; off > 0; off >>= 1) sum += __shfl_xor_sync(0xffffffffu, sum, off);
  const float inv = 1.f / sum;
#pragma unroll
  for (int t = 0; t < 7; t++) {
    const int idx = lane + t * 32;
    if (idx < 196) p[idx] = v[t] * inv;
  }
}

// ---------------- launcher ----------------
extern "C" void kernel_launch(void* const* d_in, const int* in_sizes, int n_in,
                              void* d_out, int out_size) {
  const float* x     = (const float*)d_in[0];
  const float* skip0 = (const float*)d_in[1];
  const float* skip1 = (const float*)d_in[2];
  const float* Wq    = (const float*)d_in[3];
  const float* bq    = (const float*)d_in[4];
  const float* Wk    = (const float*)d_in[5];
  const float* bk    = (const float*)d_in[6];
  const float* Wv    = (const float*)d_in[7];
  const float* bv    = (const float*)d_in[8];
  float* out = (float*)d_out;
  (void)in_sizes; (void)n_in; (void)out_size;

  // Q projection: pixels(200704) x 256, -> g_Q [n][l][c]
  mm_kernel<0><<<dim3(1792, 2), 224>>>(x, Wq, bq, nullptr, HWF, 0, 0);

  for (int s = 0; s < 2; s++) {
    const float* skip = s ? skip1 : skip0;
    const int hin = s ? 56 : 112;
    const int hwin = hin * hin;
    const int mtiles = (4 * hwin) / 112;

    mm_kernel<1><<<dim3(mtiles, 2), 224>>>(skip, Wk, bk, nullptr, hwin, 0, 0); // -> g_KL
    mm_kernel<1><<<dim3(mtiles, 2), 224>>>(skip, Wv, bv, nullptr, hwin, 0, 1); // -> g_VL
    resizeK_kernel<<<200704, 256>>>(hin, s);                                   // -> g_K[s]
    resizeV_kernel<<<dim3(7, 1024), 256>>>(hin, s);                            // -> g_Vt[s]
    mm_kernel<2><<<dim3(2, 2, 1024), 224>>>(nullptr, nullptr, nullptr, nullptr, 0, s, 0);
    softmax_kernel<<<25088, 256>>>(s);
  }
  // fused AV over both skips, unpatchified write
  mm_kernel<3><<<dim3(2, 2, 1024), 224>>>(nullptr, nullptr, nullptr, out, 0, 0, 0);
}

// round 4
// speedup vs baseline: 2.3624x; 1.3379x over previous
#include <cuda_runtime.h>
#include <cuda_bf16.h>
#include <cstdint>

#define HWF   50176
#define IMG_B 12845056

// ---------------- device scratch (split bf16 hi/lo) ----------------
__device__ unsigned short g_Qh[51380224],  g_Ql[51380224];    // [n][l][256]
__device__ unsigned short g_Kh[102760448], g_Kl[102760448];   // [s][n][m][256]
__device__ unsigned short g_Vh[117440512], g_Vl[117440512];   // [n][c][448] (s*224+m)
__device__ unsigned short g_Ph[89915392],  g_Pl[89915392];    // [n][l][448]
__device__ float g_KL[12845056], g_VL[12845056];              // lowres [b][hw][256] fp32

// ---------------- helpers ----------------
__device__ __forceinline__ void split_f32(float v, unsigned short& h, unsigned short& l) {
  __nv_bfloat16 bh = __float2bfloat16(v);
  h = __bfloat16_as_ushort(bh);
  l = __bfloat16_as_ushort(__float2bfloat16(v - __bfloat162float(bh)));
}
__device__ __forceinline__ void split2(float a, float b, unsigned& uh, unsigned& ul) {
  unsigned short h0, l0, h1, l1; split_f32(a, h0, l0); split_f32(b, h1, l1);
  uh = (unsigned)h0 | ((unsigned)h1 << 16);
  ul = (unsigned)l0 | ((unsigned)l1 << 16);
}
__device__ __forceinline__ void mma_bf16(float d[4], const unsigned a[4], const unsigned b[2]) {
  asm volatile("mma.sync.aligned.m16n8k16.row.col.f32.bf16.bf16.f32 "
               "{%0,%1,%2,%3}, {%4,%5,%6,%7}, {%8,%9}, {%0,%1,%2,%3};\n"
               : "+f"(d[0]), "+f"(d[1]), "+f"(d[2]), "+f"(d[3])
               : "r"(a[0]), "r"(a[1]), "r"(a[2]), "r"(a[3]), "r"(b[0]), "r"(b[1]));
}
#define LDSM4(r, addr) \
  asm volatile("ldmatrix.sync.aligned.m8n8.x4.shared.b16 {%0,%1,%2,%3},[%4];" \
               : "=r"(r[0]), "=r"(r[1]), "=r"(r[2]), "=r"(r[3]) : "r"(addr))
#define CP16(sm, gp, sz) \
  asm volatile("cp.async.cg.shared.global [%0],[%1],16,%2;\n" :: "r"(sm), "l"(gp), "r"(sz))
#define CPWAIT() asm volatile("cp.async.commit_group;\ncp.async.wait_group 0;\n" ::: "memory")

__device__ __forceinline__ void bilin(int n, int l, int hin,
                                      int& i00, int& i01, int& i10, int& i11,
                                      float& fh, float& fw) {
  const int ph = (n >> 4) & 15, pw = n & 15;
  const int h = ph * 14 + l / 14;
  const int w = pw * 14 + l % 14;
  const float sc = (float)hin / 224.f;
  const float sh = (h + 0.5f) * sc - 0.5f;
  const float sw = (w + 0.5f) * sc - 0.5f;
  const int ih = (int)floorf(sh), iw = (int)floorf(sw);
  fh = sh - (float)ih; fw = sw - (float)iw;
  const int h0 = max(ih, 0), h1 = min(ih + 1, hin - 1);
  const int w0 = max(iw, 0), w1 = min(iw + 1, hin - 1);
  i00 = h0 * hin + w0; i01 = h0 * hin + w1; i10 = h1 * hin + w0; i11 = h1 * hin + w1;
}

// ==================================================================
// MODE 0: Q proj  (A = x fp32 [c][hw] transp-split, B = Wq)  -> g_Qh/l [n][l][c]
// MODE 1: low proj (A = skip, B = Wk/Wv)                      -> g_KL / g_VL fp32
// MODE 2: S = Q K^T per patch, BN=200, fused softmax          -> g_Ph/l (split)
// MODE 3: O = P V^T, K=448 (both skips), transp epilogue      -> d_out
// ==================================================================
template<int MODE>
__global__ void __launch_bounds__(224, (MODE == 2) ? 1 : 2) mm_kernel(
    const float* __restrict__ Ap, const float* __restrict__ Bp,
    const float* __restrict__ bias, float* __restrict__ outp, int hwin, int which)
{
  constexpr int NF    = (MODE == 2) ? 25 : 16;
  constexpr int NCH   = (MODE == 3) ? 14 : 8;
  constexpr int BROWS = (MODE == 2) ? 208 : 128;
  constexpr int OF_BH = 17920;
  constexpr int BHB   = BROWS * 80;
  extern __shared__ __align__(16) unsigned char smem[];
  unsigned short* Ah = (unsigned short*)smem;            // [112][40]
  unsigned short* Al = (unsigned short*)(smem + 8960);
  unsigned short* Bh = (unsigned short*)(smem + OF_BH);  // [BROWS][40]
  unsigned short* Bl = (unsigned short*)(smem + OF_BH + BHB);

  const int tid = threadIdx.x, warp = tid >> 5, lane = tid & 31;
  const int qr = lane >> 2, kc2 = (lane & 3) * 2;
  const int t8 = lane >> 3, l7 = lane & 7;
  const int nz = blockIdx.z;
  const int n = (MODE == 2) ? (nz & 1023) : nz;
  const int s = (MODE == 2) ? (nz >> 10) : 0;

  const unsigned sbase  = (unsigned)__cvta_generic_to_shared(smem);
  const unsigned a_addr = sbase + ((warp * 16 + l7 + (t8 & 1) * 8) * 40 + (t8 >> 1) * 8) * 2;
  const unsigned b_addr = sbase + OF_BH + ((l7 + (t8 >> 1) * 8) * 40 + (t8 & 1) * 8) * 2;

  float acc[NF][4];
#pragma unroll
  for (int i = 0; i < NF; i++) { acc[i][0] = acc[i][1] = acc[i][2] = acc[i][3] = 0.f; }

#pragma unroll 1
  for (int ch = 0; ch < NCH; ch++) {
    const int k0 = ch * 32;
    if (MODE <= 1) {
      // A: x fp32 [c][hw] -> split transpose
      const int p0 = blockIdx.x * 112;
      const int b = p0 / hwin;
      const float* xb = Ap + (size_t)b * 256 * hwin + (p0 - b * hwin);
      for (int idx = tid; idx < 32 * 112; idx += 224) {
        const int kk = idx / 112, p = idx - kk * 112;
        unsigned short h, l; split_f32(xb[(size_t)(k0 + kk) * hwin + p], h, l);
        Ah[p * 40 + kk] = h; Al[p * 40 + kk] = l;
      }
      // B: W rows fp32 -> split
      const int o0 = blockIdx.y * 128;
      for (int idx = tid; idx < 128 * 16; idx += 224) {
        const int r = idx >> 4, cc = (idx & 15) * 2;
        float2 v = *(const float2*)&Bp[(o0 + r) * 256 + k0 + cc];
        unsigned uh, ul; split2(v.x, v.y, uh, ul);
        *(unsigned*)&Bh[r * 40 + cc] = uh;
        *(unsigned*)&Bl[r * 40 + cc] = ul;
      }
    } else if (MODE == 2) {
      const int Lb = blockIdx.x * 112;
      for (int idx = tid; idx < 112 * 4; idx += 224) {
        const int r = idx >> 2, q = (idx & 3) * 8;
        const int l = Lb + r;
        const size_t src = ((size_t)n * 196 + min(l, 195)) * 256 + k0 + q;
        const int sz = (l < 196) ? 16 : 0;
        CP16(sbase + r * 80 + q * 2, g_Qh + src, sz);
        CP16(sbase + 8960 + r * 80 + q * 2, g_Ql + src, sz);
      }
      for (int idx = tid; idx < 208 * 4; idx += 224) {
        const int r = idx >> 2, q = (idx & 3) * 8;
        const size_t src = (((size_t)s * 1024 + n) * 196 + min(r, 195)) * 256 + k0 + q;
        const int sz = (r < 196) ? 16 : 0;
        CP16(sbase + OF_BH + r * 80 + q * 2, g_Kh + src, sz);
        CP16(sbase + OF_BH + BHB + r * 80 + q * 2, g_Kl + src, sz);
      }
      CPWAIT();
    } else {
      const int Lb = blockIdx.x * 112, c0 = blockIdx.y * 128;
      for (int idx = tid; idx < 112 * 4; idx += 224) {
        const int r = idx >> 2, q = (idx & 3) * 8;
        const int l = Lb + r;
        const size_t src = ((size_t)n * 196 + min(l, 195)) * 448 + k0 + q;
        const int sz = (l < 196) ? 16 : 0;
        CP16(sbase + r * 80 + q * 2, g_Ph + src, sz);
        CP16(sbase + 8960 + r * 80 + q * 2, g_Pl + src, sz);
      }
      for (int idx = tid; idx < 128 * 4; idx += 224) {
        const int r = idx >> 2, q = (idx & 3) * 8;
        const size_t src = ((size_t)n * 256 + c0 + r) * 448 + k0 + q;
        CP16(sbase + OF_BH + r * 80 + q * 2, g_Vh + src, 16);
        CP16(sbase + OF_BH + BHB + r * 80 + q * 2, g_Vl + src, 16);
      }
      CPWAIT();
    }
    __syncthreads();
    // ---------------- MMA ----------------
#pragma unroll
    for (int kk = 0; kk < 2; kk++) {
      unsigned ah[4], al[4];
      LDSM4(ah, a_addr + kk * 32);
      LDSM4(al, a_addr + 8960 + kk * 32);
#pragma unroll
      for (int nf = 0; nf + 1 < NF; nf += 2) {
        unsigned bh[4], bl4[4];
        LDSM4(bh,  b_addr + nf * 640 + kk * 32);
        LDSM4(bl4, b_addr + BHB + nf * 640 + kk * 32);
        mma_bf16(acc[nf], ah, bh);      mma_bf16(acc[nf + 1], ah, bh + 2);
        mma_bf16(acc[nf], al, bh);      mma_bf16(acc[nf + 1], al, bh + 2);
        mma_bf16(acc[nf], ah, bl4);     mma_bf16(acc[nf + 1], ah, bl4 + 2);
      }
      if (NF & 1) {   // tail frag (MODE 2, nf = 24; rows 196..207 staged zero / unused)
        unsigned bh[4], bl4[4];
        LDSM4(bh,  b_addr + (NF - 1) * 640 + kk * 32);
        LDSM4(bl4, b_addr + BHB + (NF - 1) * 640 + kk * 32);
        mma_bf16(acc[NF - 1], ah, bh);
        mma_bf16(acc[NF - 1], al, bh);
        mma_bf16(acc[NF - 1], ah, bl4);
      }
    }
    __syncthreads();
  }

  // ---------------- epilogues ----------------
  if (MODE == 0) {
    const int p0 = blockIdx.x * 112, o0 = blockIdx.y * 128;
    const int b = p0 / hwin;
#pragma unroll
    for (int half = 0; half < 2; half++) {
      const int p = p0 + warp * 16 + qr + half * 8;
      const int pl = p - b * hwin;
      const int h = pl / 224, w = pl - (pl / 224) * 224;
      const int nn = (b << 8) + (h / 14) * 16 + (w / 14);
      const int l = (h % 14) * 14 + (w % 14);
      const size_t dst = ((size_t)nn * 196 + l) * 256;
#pragma unroll
      for (int nf = 0; nf < NF; nf++) {
        const int o = o0 + nf * 8 + kc2;
        unsigned uh, ul;
        split2(acc[nf][half * 2] + bias[o], acc[nf][half * 2 + 1] + bias[o + 1], uh, ul);
        *(unsigned*)&g_Qh[dst + o] = uh;
        *(unsigned*)&g_Ql[dst + o] = ul;
      }
    }
  } else if (MODE == 1) {
    const int p0 = blockIdx.x * 112, o0 = blockIdx.y * 128;
    float* outF = which ? g_VL : g_KL;
#pragma unroll
    for (int half = 0; half < 2; half++) {
      const int p = p0 + warp * 16 + qr + half * 8;
      float* dst = outF + (size_t)p * 256;
#pragma unroll
      for (int nf = 0; nf < NF; nf++) {
        const int o = o0 + nf * 8 + kc2;
        *(float2*)&dst[o] =
            make_float2(acc[nf][half * 2] + bias[o], acc[nf][half * 2 + 1] + bias[o + 1]);
      }
    }
  } else if (MODE == 2) {
    const int Lb = blockIdx.x * 112;
#pragma unroll
    for (int half = 0; half < 2; half++) {
      const int l = Lb + warp * 16 + qr + half * 8;
      const bool vl = (l < 196);
      float mx = -1e30f;
#pragma unroll
      for (int nf = 0; nf < NF; nf++) {
        if (nf * 8 + kc2 < 196)
          mx = fmaxf(mx, fmaxf(acc[nf][half * 2], acc[nf][half * 2 + 1]));
      }
      mx = fmaxf(mx, __shfl_xor_sync(0xffffffffu, mx, 1));
      mx = fmaxf(mx, __shfl_xor_sync(0xffffffffu, mx, 2));
      float sum = 0.f;
#pragma unroll
      for (int nf = 0; nf < NF; nf++) {
        if (nf * 8 + kc2 < 196) {
          float e0 = __expf(acc[nf][half * 2] - mx);
          float e1 = __expf(acc[nf][half * 2 + 1] - mx);
          acc[nf][half * 2] = e0; acc[nf][half * 2 + 1] = e1;
          sum += e0 + e1;
        }
      }
      sum += __shfl_xor_sync(0xffffffffu, sum, 1);
      sum += __shfl_xor_sync(0xffffffffu, sum, 2);
      const float inv = 1.f / sum;
      if (vl) {
        const size_t rb = ((size_t)n * 196 + l) * 448 + s * 224;
#pragma unroll
        for (int nf = 0; nf < 28; nf++) {
          const int m = nf * 8 + kc2;
          unsigned uh = 0, ul = 0;
          if (nf < NF && m < 196)
            split2(acc[nf][half * 2] * inv, acc[nf][half * 2 + 1] * inv, uh, ul);
          *(unsigned*)&g_Ph[rb + m] = uh;
          *(unsigned*)&g_Pl[rb + m] = ul;
        }
      }
    }
  } else {
    float* T = (float*)smem;   // [64][133]
    const int Lb = blockIdx.x * 112, c0 = blockIdx.y * 128;
    const int b = n >> 8, php = (n >> 4) & 15, pwp = n & 15;
#pragma unroll 1
    for (int pass = 0; pass < 2; pass++) {
      __syncthreads();
      if ((warp >> 2) == pass) {
        const int lr = warp * 16 + qr - pass * 64;
#pragma unroll
        for (int nf = 0; nf < NF; nf++) {
          const int c = nf * 8 + kc2;
          T[lr * 133 + c]           = acc[nf][0];
          T[lr * 133 + c + 1]       = acc[nf][1];
          T[(lr + 8) * 133 + c]     = acc[nf][2];
          T[(lr + 8) * 133 + c + 1] = acc[nf][3];
        }
      }
      __syncthreads();
      const int nrows = pass ? 48 : 64;
      for (int idx = tid; idx < 128 * 64; idx += 224) {
        const int c = idx >> 6, lr = idx & 63;
        const int l = Lb + pass * 64 + lr;
        if (lr < nrows && l < 196) {
          const int hh = php * 14 + l / 14, ww = pwp * 14 + l % 14;
          outp[(size_t)b * IMG_B + (size_t)(c0 + c) * HWF + hh * 224 + ww] = T[lr * 133 + c];
        }
      }
    }
  }
}

// ---------------- resize K: g_KL -> split g_Kh/g_Kl [s][n][m][c] ----------------
__global__ void resizeK_kernel(int hin, int s)
{
  const int r = blockIdx.x;                  // n*196 + m
  const int n = r / 196, m = r - n * 196;
  const int c2 = threadIdx.x * 2;
  int i00, i01, i10, i11; float fh, fw;
  bilin(n, m, hin, i00, i01, i10, i11, fh, fw);
  const size_t bb = (size_t)(n >> 8) * hin * hin * 256;
  const float2 a = *(const float2*)&g_KL[bb + (size_t)i00 * 256 + c2];
  const float2 b = *(const float2*)&g_KL[bb + (size_t)i01 * 256 + c2];
  const float2 c = *(const float2*)&g_KL[bb + (size_t)i10 * 256 + c2];
  const float2 d = *(const float2*)&g_KL[bb + (size_t)i11 * 256 + c2];
  const float w00 = (1.f - fh) * (1.f - fw), w01 = (1.f - fh) * fw;
  const float w10 = fh * (1.f - fw), w11 = fh * fw;
  unsigned uh, ul;
  split2(w00 * a.x + w01 * b.x + w10 * c.x + w11 * d.x,
         w00 * a.y + w01 * b.y + w10 * c.y + w11 * d.y, uh, ul);
  const size_t dst = (((size_t)s * 1024 + n) * 196 + m) * 256 + c2;
  *(unsigned*)&g_Kh[dst] = uh;
  *(unsigned*)&g_Kl[dst] = ul;
}

// ---------------- resize V + transpose: g_VL -> split g_Vh/g_Vl [n][c][448] ----------------
__global__ void resizeV_kernel(int hin, int s)
{
  __shared__ float sm[28 * 257];
  const int mt = blockIdx.x;      // 0..7 (7 = zero pad)
  const int n = blockIdx.y;
  const int c = threadIdx.x;      // 256
  if (mt == 7) {
    const size_t base = ((size_t)n * 256 + c) * 448 + s * 224 + 196;
#pragma unroll
    for (int i = 0; i < 14; i++) {
      *(unsigned*)&g_Vh[base + i * 2] = 0u;
      *(unsigned*)&g_Vl[base + i * 2] = 0u;
    }
    return;
  }
  const size_t bb = (size_t)(n >> 8) * hin * hin * 256;
#pragma unroll 1
  for (int li = 0; li < 28; li++) {
    int i00, i01, i10, i11; float fh, fw;
    bilin(n, mt * 28 + li, hin, i00, i01, i10, i11, fh, fw);
    const float v00 = g_VL[bb + (size_t)i00 * 256 + c], v01 = g_VL[bb + (size_t)i01 * 256 + c];
    const float v10 = g_VL[bb + (size_t)i10 * 256 + c], v11 = g_VL[bb + (size_t)i11 * 256 + c];
    sm[li * 257 + c] = (1.f - fh) * ((1.f - fw) * v00 + fw * v01)
                     + fh * ((1.f - fw) * v10 + fw * v11);
  }
  __syncthreads();
  for (int idx = c; idx < 14 * 256; idx += 256) {
    const int cc = idx / 14, li2 = (idx - cc * 14) * 2;
    unsigned uh, ul;
    split2(sm[li2 * 257 + cc], sm[(li2 + 1) * 257 + cc], uh, ul);
    const size_t dst = ((size_t)n * 256 + cc) * 448 + s * 224 + mt * 28 + li2;
    *(unsigned*)&g_Vh[dst] = uh;
    *(unsigned*)&g_Vl[dst] = ul;
  }
}

// ---------------- launcher ----------------
extern "C" void kernel_launch(void* const* d_in, const int* in_sizes, int n_in,
                              void* d_out, int out_size) {
  const float* x     = (const float*)d_in[0];
  const float* skip0 = (const float*)d_in[1];
  const float* skip1 = (const float*)d_in[2];
  const float* Wq    = (const float*)d_in[3];
  const float* bq    = (const float*)d_in[4];
  const float* Wk    = (const float*)d_in[5];
  const float* bk    = (const float*)d_in[6];
  const float* Wv    = (const float*)d_in[7];
  const float* bv    = (const float*)d_in[8];
  float* out = (float*)d_out;
  (void)in_sizes; (void)n_in; (void)out_size;

  static int inited = 0;
  if (!inited) {
    cudaFuncSetAttribute(mm_kernel<2>, cudaFuncAttributeMaxDynamicSharedMemorySize, 51200);
    inited = 1;
  }

  mm_kernel<0><<<dim3(1792, 2), 224, 38400>>>(x, Wq, bq, nullptr, HWF, 0);

  for (int s = 0; s < 2; s++) {
    const float* skip = s ? skip1 : skip0;
    const int hin = s ? 56 : 112;
    const int hwin = hin * hin;
    const int mtiles = (4 * hwin) / 112;
    mm_kernel<1><<<dim3(mtiles, 2), 224, 38400>>>(skip, Wk, bk, nullptr, hwin, 0);
    mm_kernel<1><<<dim3(mtiles, 2), 224, 38400>>>(skip, Wv, bv, nullptr, hwin, 1);
    resizeK_kernel<<<200704, 128>>>(hin, s);
    resizeV_kernel<<<dim3(8, 1024), 256>>>(hin, s);
  }

  // S + fused softmax (both skips in z), then fused AV -> out
  mm_kernel<2><<<dim3(2, 1, 2048), 224, 51200>>>(nullptr, nullptr, nullptr, nullptr, 0, 0);
  mm_kernel<3><<<dim3(2, 2, 1024), 224, 38400>>>(nullptr, nullptr, nullptr, out, 0, 0);
}

// round 5
// speedup vs baseline: 2.6181x; 1.1082x over previous
#include <cuda_runtime.h>
#include <cuda_bf16.h>
#include <cstdint>

#define HWF   50176
#define IMG_B 12845056

// ---------------- device scratch (split bf16 hi/lo) ----------------
__device__ unsigned short g_Qh[51380224],  g_Ql[51380224];    // [n][l][256]
__device__ unsigned short g_Kh[102760448], g_Kl[102760448];   // [s][n][m][256]
__device__ unsigned short g_Vh[109051904], g_Vl[109051904];   // [n][c][416] (s*196+m)
__device__ unsigned short g_Ph[83492864],  g_Pl[83492864];    // [n][l][416]
__device__ float g_KL[12845056], g_VL[12845056];              // lowres [b][hw][256] fp32

// ---------------- helpers ----------------
__device__ __forceinline__ void split_f32(float v, unsigned short& h, unsigned short& l) {
  __nv_bfloat16 bh = __float2bfloat16(v);
  h = __bfloat16_as_ushort(bh);
  l = __bfloat16_as_ushort(__float2bfloat16(v - __bfloat162float(bh)));
}
__device__ __forceinline__ void split2(float a, float b, unsigned& uh, unsigned& ul) {
  unsigned short h0, l0, h1, l1; split_f32(a, h0, l0); split_f32(b, h1, l1);
  uh = (unsigned)h0 | ((unsigned)h1 << 16);
  ul = (unsigned)l0 | ((unsigned)l1 << 16);
}
__device__ __forceinline__ void mma_bf16(float d[4], const unsigned a[4], const unsigned b[2]) {
  asm volatile("mma.sync.aligned.m16n8k16.row.col.f32.bf16.bf16.f32 "
               "{%0,%1,%2,%3}, {%4,%5,%6,%7}, {%8,%9}, {%0,%1,%2,%3};\n"
               : "+f"(d[0]), "+f"(d[1]), "+f"(d[2]), "+f"(d[3])
               : "r"(a[0]), "r"(a[1]), "r"(a[2]), "r"(a[3]), "r"(b[0]), "r"(b[1]));
}
#define LDSM4(r, addr) \
  asm volatile("ldmatrix.sync.aligned.m8n8.x4.shared.b16 {%0,%1,%2,%3},[%4];" \
               : "=r"(r[0]), "=r"(r[1]), "=r"(r[2]), "=r"(r[3]) : "r"(addr))
#define CP16(sm, gp, sz) \
  asm volatile("cp.async.cg.shared.global [%0],[%1],16,%2;\n" :: "r"(sm), "l"(gp), "r"(sz))
#define CPCOMMIT() asm volatile("cp.async.commit_group;\n" ::: "memory")
#define CPWAIT1()  asm volatile("cp.async.wait_group 1;\n" ::: "memory")
#define CPWAIT0()  asm volatile("cp.async.wait_group 0;\n" ::: "memory")

__device__ __forceinline__ void bilin(int n, int l, int hin,
                                      int& i00, int& i01, int& i10, int& i11,
                                      float& fh, float& fw) {
  const int ph = (n >> 4) & 15, pw = n & 15;
  const int h = ph * 14 + l / 14;
  const int w = pw * 14 + l % 14;
  const float sc = (float)hin / 224.f;
  const float sh = (h + 0.5f) * sc - 0.5f;
  const float sw = (w + 0.5f) * sc - 0.5f;
  const int ih = (int)floorf(sh), iw = (int)floorf(sw);
  fh = sh - (float)ih; fw = sw - (float)iw;
  const int h0 = max(ih, 0), h1 = min(ih + 1, hin - 1);
  const int w0 = max(iw, 0), w1 = min(iw + 1, hin - 1);
  i00 = h0 * hin + w0; i01 = h0 * hin + w1; i10 = h1 * hin + w0; i11 = h1 * hin + w1;
}

// ==================================================================
// MODE 0: Q proj  (A = x fp32 [c][hw] transp-split, B = Wq)  -> g_Qh/l [n][l][c]
// MODE 1: low proj (A = skip, B = Wk/Wv)                      -> g_KL / g_VL fp32
// MODE 2: S = Q K^T per patch, BN=200, fused softmax, 2-stage -> g_Ph/l (split)
// MODE 3: O = P V^T, K=416 (both skips), 2-stage, transp epi  -> d_out
// ==================================================================
template<int MODE>
__global__ void __launch_bounds__(224, (MODE == 2) ? 1 : 2) mm_kernel(
    const float* __restrict__ Ap, const float* __restrict__ Bp,
    const float* __restrict__ bias, float* __restrict__ outp, int hwin, int which)
{
  constexpr int NF    = (MODE == 2) ? 25 : 16;
  constexpr int NCH   = (MODE == 3) ? 13 : 8;
  constexpr int BROWS = (MODE == 2) ? 208 : 128;
  constexpr int OF_BH = 17920;
  constexpr int BHB   = BROWS * 80;
  constexpr int BUFSZ = OF_BH + 2 * BHB;       // 51200 (M2) / 38400 (M3)
  extern __shared__ __align__(16) unsigned char smem[];
  unsigned short* Ah = (unsigned short*)smem;            // [112][40]
  unsigned short* Al = (unsigned short*)(smem + 8960);
  unsigned short* Bh = (unsigned short*)(smem + OF_BH);  // [BROWS][40]
  unsigned short* Bl = (unsigned short*)(smem + OF_BH + BHB);

  const int tid = threadIdx.x, warp = tid >> 5, lane = tid & 31;
  const int qr = lane >> 2, kc2 = (lane & 3) * 2;
  const int t8 = lane >> 3, l7 = lane & 7;
  const int nz = blockIdx.z;
  const int n = (MODE == 2) ? (nz & 1023) : nz;
  const int s = (MODE == 2) ? (nz >> 10) : 0;

  const unsigned sbase  = (unsigned)__cvta_generic_to_shared(smem);
  const unsigned a_addr = sbase + ((warp * 16 + l7 + (t8 & 1) * 8) * 40 + (t8 >> 1) * 8) * 2;
  const unsigned b_addr = sbase + OF_BH + ((l7 + (t8 >> 1) * 8) * 40 + (t8 & 1) * 8) * 2;

  float acc[NF][4];
#pragma unroll
  for (int i = 0; i < NF; i++) { acc[i][0] = acc[i][1] = acc[i][2] = acc[i][3] = 0.f; }

  // ----- shared MMA step -----
  auto domma = [&](unsigned ao, unsigned bo) {
#pragma unroll
    for (int kk = 0; kk < 2; kk++) {
      unsigned ah[4], al[4];
      LDSM4(ah, ao + kk * 32);
      LDSM4(al, ao + 8960 + kk * 32);
#pragma unroll
      for (int nf = 0; nf + 1 < NF; nf += 2) {
        unsigned bh[4], bl4[4];
        LDSM4(bh,  bo + nf * 640 + kk * 32);
        LDSM4(bl4, bo + BHB + nf * 640 + kk * 32);
        mma_bf16(acc[nf], ah, bh);      mma_bf16(acc[nf + 1], ah, bh + 2);
        mma_bf16(acc[nf], al, bh);      mma_bf16(acc[nf + 1], al, bh + 2);
        mma_bf16(acc[nf], ah, bl4);     mma_bf16(acc[nf + 1], ah, bl4 + 2);
      }
      if (NF & 1) {
        unsigned bh[4], bl4[4];
        LDSM4(bh,  bo + (NF - 1) * 640 + kk * 32);
        LDSM4(bl4, bo + BHB + (NF - 1) * 640 + kk * 32);
        mma_bf16(acc[NF - 1], ah, bh);
        mma_bf16(acc[NF - 1], al, bh);
        mma_bf16(acc[NF - 1], ah, bl4);
      }
    }
  };

  if (MODE <= 1) {
#pragma unroll 1
    for (int ch = 0; ch < NCH; ch++) {
      const int k0 = ch * 32;
      const int p0 = blockIdx.x * 112;
      const int b = p0 / hwin;
      const float* xb = Ap + (size_t)b * 256 * hwin + (p0 - b * hwin);
      for (int idx = tid; idx < 32 * 112; idx += 224) {
        const int kk = idx / 112, p = idx - kk * 112;
        unsigned short h, l; split_f32(xb[(size_t)(k0 + kk) * hwin + p], h, l);
        Ah[p * 40 + kk] = h; Al[p * 40 + kk] = l;
      }
      const int o0 = blockIdx.y * 128;
      for (int idx = tid; idx < 128 * 16; idx += 224) {
        const int r = idx >> 4, cc = (idx & 15) * 2;
        float2 v = *(const float2*)&Bp[(o0 + r) * 256 + k0 + cc];
        unsigned uh, ul; split2(v.x, v.y, uh, ul);
        *(unsigned*)&Bh[r * 40 + cc] = uh;
        *(unsigned*)&Bl[r * 40 + cc] = ul;
      }
      __syncthreads();
      domma(a_addr, b_addr);
      __syncthreads();
    }
  } else {
    const int Lb = blockIdx.x * 112;
    const int c0 = blockIdx.y * 128;
    auto stage = [&](int ch, int buf) {
      const unsigned sb = sbase + (unsigned)buf * BUFSZ;
      const int k0 = ch * 32;
      if (MODE == 2) {
        for (int idx = tid; idx < 112 * 4; idx += 224) {
          const int r = idx >> 2, q = (idx & 3) * 8;
          const int l = Lb + r;
          const size_t src = ((size_t)n * 196 + min(l, 195)) * 256 + k0 + q;
          const int sz = (l < 196) ? 16 : 0;
          CP16(sb + r * 80 + q * 2, g_Qh + src, sz);
          CP16(sb + 8960 + r * 80 + q * 2, g_Ql + src, sz);
        }
        for (int idx = tid; idx < 208 * 4; idx += 224) {
          const int r = idx >> 2, q = (idx & 3) * 8;
          const size_t src = (((size_t)s * 1024 + n) * 196 + min(r, 195)) * 256 + k0 + q;
          const int sz = (r < 196) ? 16 : 0;
          CP16(sb + OF_BH + r * 80 + q * 2, g_Kh + src, sz);
          CP16(sb + OF_BH + BHB + r * 80 + q * 2, g_Kl + src, sz);
        }
      } else {
        for (int idx = tid; idx < 112 * 4; idx += 224) {
          const int r = idx >> 2, q = (idx & 3) * 8;
          const int l = Lb + r;
          const size_t src = ((size_t)n * 196 + min(l, 195)) * 416 + k0 + q;
          const int sz = (l < 196) ? 16 : 0;
          CP16(sb + r * 80 + q * 2, g_Ph + src, sz);
          CP16(sb + 8960 + r * 80 + q * 2, g_Pl + src, sz);
        }
        for (int idx = tid; idx < 128 * 4; idx += 224) {
          const int r = idx >> 2, q = (idx & 3) * 8;
          const size_t src = ((size_t)n * 256 + c0 + r) * 416 + k0 + q;
          CP16(sb + OF_BH + r * 80 + q * 2, g_Vh + src, 16);
          CP16(sb + OF_BH + BHB + r * 80 + q * 2, g_Vl + src, 16);
        }
      }
      CPCOMMIT();
    };
    stage(0, 0);
#pragma unroll 1
    for (int ch = 0; ch < NCH; ch++) {
      const int buf = ch & 1;
      if (ch + 1 < NCH) { stage(ch + 1, buf ^ 1); CPWAIT1(); }
      else              { CPWAIT0(); }
      __syncthreads();
      domma(a_addr + (unsigned)buf * BUFSZ, b_addr + (unsigned)buf * BUFSZ);
      __syncthreads();
    }
  }

  // ---------------- epilogues ----------------
  if (MODE == 0) {
    const int p0 = blockIdx.x * 112, o0 = blockIdx.y * 128;
    const int b = p0 / hwin;
#pragma unroll
    for (int half = 0; half < 2; half++) {
      const int p = p0 + warp * 16 + qr + half * 8;
      const int pl = p - b * hwin;
      const int h = pl / 224, w = pl - (pl / 224) * 224;
      const int nn = (b << 8) + (h / 14) * 16 + (w / 14);
      const int l = (h % 14) * 14 + (w % 14);
      const size_t dst = ((size_t)nn * 196 + l) * 256;
#pragma unroll
      for (int nf = 0; nf < NF; nf++) {
        const int o = o0 + nf * 8 + kc2;
        unsigned uh, ul;
        split2(acc[nf][half * 2] + bias[o], acc[nf][half * 2 + 1] + bias[o + 1], uh, ul);
        *(unsigned*)&g_Qh[dst + o] = uh;
        *(unsigned*)&g_Ql[dst + o] = ul;
      }
    }
  } else if (MODE == 1) {
    const int p0 = blockIdx.x * 112, o0 = blockIdx.y * 128;
    float* outF = which ? g_VL : g_KL;
#pragma unroll
    for (int half = 0; half < 2; half++) {
      const int p = p0 + warp * 16 + qr + half * 8;
      float* dst = outF + (size_t)p * 256;
#pragma unroll
      for (int nf = 0; nf < NF; nf++) {
        const int o = o0 + nf * 8 + kc2;
        *(float2*)&dst[o] =
            make_float2(acc[nf][half * 2] + bias[o], acc[nf][half * 2 + 1] + bias[o + 1]);
      }
    }
  } else if (MODE == 2) {
    const int Lb = blockIdx.x * 112;
#pragma unroll
    for (int half = 0; half < 2; half++) {
      const int l = Lb + warp * 16 + qr + half * 8;
      const bool vl = (l < 196);
      float mx = -1e30f;
#pragma unroll
      for (int nf = 0; nf < NF; nf++) {
        if (nf * 8 + kc2 < 196)
          mx = fmaxf(mx, fmaxf(acc[nf][half * 2], acc[nf][half * 2 + 1]));
      }
      mx = fmaxf(mx, __shfl_xor_sync(0xffffffffu, mx, 1));
      mx = fmaxf(mx, __shfl_xor_sync(0xffffffffu, mx, 2));
      float sum = 0.f;
#pragma unroll
      for (int nf = 0; nf < NF; nf++) {
        if (nf * 8 + kc2 < 196) {
          float e0 = __expf(acc[nf][half * 2] - mx);
          float e1 = __expf(acc[nf][half * 2 + 1] - mx);
          acc[nf][half * 2] = e0; acc[nf][half * 2 + 1] = e1;
          sum += e0 + e1;
        }
      }
      sum += __shfl_xor_sync(0xffffffffu, sum, 1);
      sum += __shfl_xor_sync(0xffffffffu, sum, 2);
      const float inv = 1.f / sum;
      if (vl) {
        const size_t rb0 = ((size_t)n * 196 + l) * 416;
        const size_t rb  = rb0 + s * 196;
#pragma unroll
        for (int nf = 0; nf < NF; nf++) {
          const int m = nf * 8 + kc2;
          if (m < 196) {
            unsigned uh, ul;
            split2(acc[nf][half * 2] * inv, acc[nf][half * 2 + 1] * inv, uh, ul);
            *(unsigned*)&g_Ph[rb + m] = uh;
            *(unsigned*)&g_Pl[rb + m] = ul;
          }
        }
        if (s == 1) {   // zero the 392..415 pad once per row
#pragma unroll
          for (int i = 0; i < 3; i++) {
            *(unsigned*)&g_Ph[rb0 + 392 + i * 8 + kc2] = 0u;
            *(unsigned*)&g_Pl[rb0 + 392 + i * 8 + kc2] = 0u;
          }
        }
      }
    }
  } else {
    float* T = (float*)smem;   // [64][133]
    const int Lb = blockIdx.x * 112, c0 = blockIdx.y * 128;
    const int b = n >> 8, php = (n >> 4) & 15, pwp = n & 15;
#pragma unroll 1
    for (int pass = 0; pass < 2; pass++) {
      __syncthreads();
      if ((warp >> 2) == pass) {
        const int lr = warp * 16 + qr - pass * 64;
#pragma unroll
        for (int nf = 0; nf < NF; nf++) {
          const int c = nf * 8 + kc2;
          T[lr * 133 + c]           = acc[nf][0];
          T[lr * 133 + c + 1]       = acc[nf][1];
          T[(lr + 8) * 133 + c]     = acc[nf][2];
          T[(lr + 8) * 133 + c + 1] = acc[nf][3];
        }
      }
      __syncthreads();
      const int nrows = pass ? 48 : 64;
      for (int idx = tid; idx < 128 * 64; idx += 224) {
        const int c = idx >> 6, lr = idx & 63;
        const int l = Lb + pass * 64 + lr;
        if (lr < nrows && l < 196) {
          const int hh = php * 14 + l / 14, ww = pwp * 14 + l % 14;
          outp[(size_t)b * IMG_B + (size_t)(c0 + c) * HWF + hh * 224 + ww] = T[lr * 133 + c];
        }
      }
    }
  }
}

// ---------------- resize K: g_KL -> split g_Kh/g_Kl [s][n][m][c] ----------------
__global__ void resizeK_kernel(int hin, int s)
{
  const int r = blockIdx.x;                  // n*196 + m
  const int n = r / 196, m = r - n * 196;
  const int c4 = threadIdx.x * 4;            // 64 threads
  int i00, i01, i10, i11; float fh, fw;
  bilin(n, m, hin, i00, i01, i10, i11, fh, fw);
  const size_t bb = (size_t)(n >> 8) * hin * hin * 256;
  const float4 a = *(const float4*)&g_KL[bb + (size_t)i00 * 256 + c4];
  const float4 b = *(const float4*)&g_KL[bb + (size_t)i01 * 256 + c4];
  const float4 c = *(const float4*)&g_KL[bb + (size_t)i10 * 256 + c4];
  const float4 d = *(const float4*)&g_KL[bb + (size_t)i11 * 256 + c4];
  const float w00 = (1.f - fh) * (1.f - fw), w01 = (1.f - fh) * fw;
  const float w10 = fh * (1.f - fw), w11 = fh * fw;
  unsigned uh0, ul0, uh1, ul1;
  split2(w00 * a.x + w01 * b.x + w10 * c.x + w11 * d.x,
         w00 * a.y + w01 * b.y + w10 * c.y + w11 * d.y, uh0, ul0);
  split2(w00 * a.z + w01 * b.z + w10 * c.z + w11 * d.z,
         w00 * a.w + w01 * b.w + w10 * c.w + w11 * d.w, uh1, ul1);
  const size_t dst = (((size_t)s * 1024 + n) * 196 + m) * 256 + c4;
  *(uint2*)&g_Kh[dst] = make_uint2(uh0, uh1);
  *(uint2*)&g_Kl[dst] = make_uint2(ul0, ul1);
}

// ---------------- resize V + transpose: g_VL -> split g_Vh/g_Vl [n][c][416] ----------------
__global__ void resizeV_kernel(int hin, int s)
{
  __shared__ float sm[28 * 257];
  const int mt = blockIdx.x;      // 0..6 (7 = zero pad, s==1 launch only)
  const int n = blockIdx.y;
  const int c = threadIdx.x;      // 256
  if (mt == 7) {
    const size_t base = ((size_t)n * 256 + c) * 416 + 392;
#pragma unroll
    for (int i = 0; i < 12; i++) {
      *(unsigned*)&g_Vh[base + i * 2] = 0u;
      *(unsigned*)&g_Vl[base + i * 2] = 0u;
    }
    return;
  }
  const size_t bb = (size_t)(n >> 8) * hin * hin * 256;
#pragma unroll 1
  for (int li = 0; li < 28; li++) {
    int i00, i01, i10, i11; float fh, fw;
    bilin(n, mt * 28 + li, hin, i00, i01, i10, i11, fh, fw);
    const float v00 = g_VL[bb + (size_t)i00 * 256 + c], v01 = g_VL[bb + (size_t)i01 * 256 + c];
    const float v10 = g_VL[bb + (size_t)i10 * 256 + c], v11 = g_VL[bb + (size_t)i11 * 256 + c];
    sm[li * 257 + c] = (1.f - fh) * ((1.f - fw) * v00 + fw * v01)
                     + fh * ((1.f - fw) * v10 + fw * v11);
  }
  __syncthreads();
  for (int idx = c; idx < 14 * 256; idx += 256) {
    const int cc = idx / 14, li2 = (idx - cc * 14) * 2;
    unsigned uh, ul;
    split2(sm[li2 * 257 + cc], sm[(li2 + 1) * 257 + cc], uh, ul);
    const size_t dst = ((size_t)n * 256 + cc) * 416 + s * 196 + mt * 28 + li2;
    *(unsigned*)&g_Vh[dst] = uh;
    *(unsigned*)&g_Vl[dst] = ul;
  }
}

// ---------------- launcher ----------------
extern "C" void kernel_launch(void* const* d_in, const int* in_sizes, int n_in,
                              void* d_out, int out_size) {
  const float* x     = (const float*)d_in[0];
  const float* skip0 = (const float*)d_in[1];
  const float* skip1 = (const float*)d_in[2];
  const float* Wq    = (const float*)d_in[3];
  const float* bq    = (const float*)d_in[4];
  const float* Wk    = (const float*)d_in[5];
  const float* bk    = (const float*)d_in[6];
  const float* Wv    = (const float*)d_in[7];
  const float* bv    = (const float*)d_in[8];
  float* out = (float*)d_out;
  (void)in_sizes; (void)n_in; (void)out_size;

  static int inited = 0;
  if (!inited) {
    cudaFuncSetAttribute(mm_kernel<2>, cudaFuncAttributeMaxDynamicSharedMemorySize, 102400);
    cudaFuncSetAttribute(mm_kernel<3>, cudaFuncAttributeMaxDynamicSharedMemorySize, 76800);
    inited = 1;
  }

  mm_kernel<0><<<dim3(1792, 2), 224, 38400>>>(x, Wq, bq, nullptr, HWF, 0);

  for (int s = 0; s < 2; s++) {
    const float* skip = s ? skip1 : skip0;
    const int hin = s ? 56 : 112;
    const int hwin = hin * hin;
    const int mtiles = (4 * hwin) / 112;
    mm_kernel<1><<<dim3(mtiles, 2), 224, 38400>>>(skip, Wk, bk, nullptr, hwin, 0);
    mm_kernel<1><<<dim3(mtiles, 2), 224, 38400>>>(skip, Wv, bv, nullptr, hwin, 1);
    resizeK_kernel<<<200704, 64>>>(hin, s);
    resizeV_kernel<<<dim3(7 + s, 1024), 256>>>(hin, s);
  }

  // S + fused softmax (both skips in z), then fused AV -> out
  mm_kernel<2><<<dim3(2, 1, 2048), 224, 102400>>>(nullptr, nullptr, nullptr, nullptr, 0, 0);
  mm_kernel<3><<<dim3(2, 2, 1024), 224, 76800>>>(nullptr, nullptr, nullptr, out, 0, 0);
}

// round 6
// speedup vs baseline: 2.6192x; 1.0004x over previous
#include <cuda_runtime.h>
#include <cuda_bf16.h>
#include <cstdint>

#define HWF   50176
#define IMG_B 12845056

// ---------------- device scratch (split bf16 hi/lo) ----------------
__device__ unsigned short g_Qh[51380224],  g_Ql[51380224];    // [n][l][256]
__device__ unsigned short g_Kh[102760448], g_Kl[102760448];   // [s][n][m][256]
__device__ unsigned short g_Vh[109051904], g_Vl[109051904];   // [n][c][416] (s*196+m)
__device__ unsigned short g_Ph[83492864],  g_Pl[83492864];    // [n][l][416]
__device__ float g_KL[12845056], g_VL[12845056];              // lowres [b][hw][256] fp32

// ---------------- helpers ----------------
__device__ __forceinline__ void split_f32(float v, unsigned short& h, unsigned short& l) {
  __nv_bfloat16 bh = __float2bfloat16(v);
  h = __bfloat16_as_ushort(bh);
  l = __bfloat16_as_ushort(__float2bfloat16(v - __bfloat162float(bh)));
}
__device__ __forceinline__ void split2(float a, float b, unsigned& uh, unsigned& ul) {
  unsigned short h0, l0, h1, l1; split_f32(a, h0, l0); split_f32(b, h1, l1);
  uh = (unsigned)h0 | ((unsigned)h1 << 16);
  ul = (unsigned)l0 | ((unsigned)l1 << 16);
}
__device__ __forceinline__ void mma_bf16(float d[4], const unsigned a[4], const unsigned b[2]) {
  asm volatile("mma.sync.aligned.m16n8k16.row.col.f32.bf16.bf16.f32 "
               "{%0,%1,%2,%3}, {%4,%5,%6,%7}, {%8,%9}, {%0,%1,%2,%3};\n"
               : "+f"(d[0]), "+f"(d[1]), "+f"(d[2]), "+f"(d[3])
               : "r"(a[0]), "r"(a[1]), "r"(a[2]), "r"(a[3]), "r"(b[0]), "r"(b[1]));
}
#define LDSM4(r, addr) \
  asm volatile("ldmatrix.sync.aligned.m8n8.x4.shared.b16 {%0,%1,%2,%3},[%4];" \
               : "=r"(r[0]), "=r"(r[1]), "=r"(r[2]), "=r"(r[3]) : "r"(addr))
#define CP16(sm, gp, sz) \
  asm volatile("cp.async.cg.shared.global [%0],[%1],16,%2;\n" :: "r"(sm), "l"(gp), "r"(sz))
#define CPCOMMIT() asm volatile("cp.async.commit_group;\n" ::: "memory")
#define CPWAIT1()  asm volatile("cp.async.wait_group 1;\n" ::: "memory")
#define CPWAIT0()  asm volatile("cp.async.wait_group 0;\n" ::: "memory")

__device__ __forceinline__ void bilin(int n, int l, int hin,
                                      int& i00, int& i01, int& i10, int& i11,
                                      float& fh, float& fw) {
  const int ph = (n >> 4) & 15, pw = n & 15;
  const int h = ph * 14 + l / 14;
  const int w = pw * 14 + l % 14;
  const float sc = (float)hin / 224.f;
  const float sh = (h + 0.5f) * sc - 0.5f;
  const float sw = (w + 0.5f) * sc - 0.5f;
  const int ih = (int)floorf(sh), iw = (int)floorf(sw);
  fh = sh - (float)ih; fw = sw - (float)iw;
  const int h0 = max(ih, 0), h1 = min(ih + 1, hin - 1);
  const int w0 = max(iw, 0), w1 = min(iw + 1, hin - 1);
  i00 = h0 * hin + w0; i01 = h0 * hin + w1; i10 = h1 * hin + w0; i11 = h1 * hin + w1;
}

// ==================================================================
// MODE 0: Q proj  (A = x fp32 [c][hw] transp-split, B = Wq)  -> g_Qh/l [n][l][c]
// MODE 1: low proj (A = skip, B = Wk/Wv)                      -> g_KL / g_VL fp32
// MODE 2: S = Q K^T per patch, BN=200, fused softmax, 2-stage -> g_Ph/l (split)
// MODE 3: O = P V^T, K=416 (both skips), 2-stage, transp epi  -> d_out
// ==================================================================
template<int MODE>
__global__ void __launch_bounds__(224, (MODE == 2) ? 1 : 2) mm_kernel(
    const float* __restrict__ Ap, const float* __restrict__ Bp,
    const float* __restrict__ bias, float* __restrict__ outp, int hwin, int which)
{
  constexpr int NF    = (MODE == 2) ? 25 : 16;
  constexpr int NCH   = (MODE == 3) ? 13 : 8;
  constexpr int BROWS = (MODE == 2) ? 208 : 128;
  constexpr int OF_BH = 17920;
  constexpr int BHB   = BROWS * 80;
  constexpr int BUFSZ = OF_BH + 2 * BHB;       // 51200 (M2) / 38400 (M3)
  extern __shared__ __align__(16) unsigned char smem[];
  unsigned short* Ah = (unsigned short*)smem;            // [112][40]
  unsigned short* Al = (unsigned short*)(smem + 8960);
  unsigned short* Bh = (unsigned short*)(smem + OF_BH);  // [BROWS][40]
  unsigned short* Bl = (unsigned short*)(smem + OF_BH + BHB);

  const int tid = threadIdx.x, warp = tid >> 5, lane = tid & 31;
  const int qr = lane >> 2, kc2 = (lane & 3) * 2;
  const int t8 = lane >> 3, l7 = lane & 7;
  const int nz = blockIdx.z;
  const int n = (MODE == 2) ? (nz & 1023) : nz;
  const int s = (MODE == 2) ? (nz >> 10) : 0;

  const unsigned sbase  = (unsigned)__cvta_generic_to_shared(smem);
  const unsigned a_addr = sbase + ((warp * 16 + l7 + (t8 & 1) * 8) * 40 + (t8 >> 1) * 8) * 2;
  const unsigned b_addr = sbase + OF_BH + ((l7 + (t8 >> 1) * 8) * 40 + (t8 & 1) * 8) * 2;

  float acc[NF][4];
#pragma unroll
  for (int i = 0; i < NF; i++) { acc[i][0] = acc[i][1] = acc[i][2] = acc[i][3] = 0.f; }

  // ----- shared MMA step -----
  auto domma = [&](unsigned ao, unsigned bo) {
#pragma unroll
    for (int kk = 0; kk < 2; kk++) {
      unsigned ah[4], al[4];
      LDSM4(ah, ao + kk * 32);
      LDSM4(al, ao + 8960 + kk * 32);
#pragma unroll
      for (int nf = 0; nf + 1 < NF; nf += 2) {
        unsigned bh[4], bl4[4];
        LDSM4(bh,  bo + nf * 640 + kk * 32);
        LDSM4(bl4, bo + BHB + nf * 640 + kk * 32);
        mma_bf16(acc[nf], ah, bh);      mma_bf16(acc[nf + 1], ah, bh + 2);
        mma_bf16(acc[nf], al, bh);      mma_bf16(acc[nf + 1], al, bh + 2);
        mma_bf16(acc[nf], ah, bl4);     mma_bf16(acc[nf + 1], ah, bl4 + 2);
      }
      if (NF & 1) {
        unsigned bh[4], bl4[4];
        LDSM4(bh,  bo + (NF - 1) * 640 + kk * 32);
        LDSM4(bl4, bo + BHB + (NF - 1) * 640 + kk * 32);
        mma_bf16(acc[NF - 1], ah, bh);
        mma_bf16(acc[NF - 1], al, bh);
        mma_bf16(acc[NF - 1], ah, bl4);
      }
    }
  };

  if (MODE <= 1) {
#pragma unroll 1
    for (int ch = 0; ch < NCH; ch++) {
      const int k0 = ch * 32;
      const int p0 = blockIdx.x * 112;
      const int b = p0 / hwin;
      const float* xb = Ap + (size_t)b * 256 * hwin + (p0 - b * hwin);
      for (int idx = tid; idx < 32 * 112; idx += 224) {
        const int kk = idx / 112, p = idx - kk * 112;
        unsigned short h, l; split_f32(xb[(size_t)(k0 + kk) * hwin + p], h, l);
        Ah[p * 40 + kk] = h; Al[p * 40 + kk] = l;
      }
      const int o0 = blockIdx.y * 128;
      for (int idx = tid; idx < 128 * 16; idx += 224) {
        const int r = idx >> 4, cc = (idx & 15) * 2;
        float2 v = *(const float2*)&Bp[(o0 + r) * 256 + k0 + cc];
        unsigned uh, ul; split2(v.x, v.y, uh, ul);
        *(unsigned*)&Bh[r * 40 + cc] = uh;
        *(unsigned*)&Bl[r * 40 + cc] = ul;
      }
      __syncthreads();
      domma(a_addr, b_addr);
      __syncthreads();
    }
  } else {
    const int Lb = blockIdx.x * 112;
    const int c0 = blockIdx.y * 128;
    auto stage = [&](int ch, int buf) {
      const unsigned sb = sbase + (unsigned)buf * BUFSZ;
      const int k0 = ch * 32;
      if (MODE == 2) {
        for (int idx = tid; idx < 112 * 4; idx += 224) {
          const int r = idx >> 2, q = (idx & 3) * 8;
          const int l = Lb + r;
          const size_t src = ((size_t)n * 196 + min(l, 195)) * 256 + k0 + q;
          const int sz = (l < 196) ? 16 : 0;
          CP16(sb + r * 80 + q * 2, g_Qh + src, sz);
          CP16(sb + 8960 + r * 80 + q * 2, g_Ql + src, sz);
        }
        for (int idx = tid; idx < 208 * 4; idx += 224) {
          const int r = idx >> 2, q = (idx & 3) * 8;
          const size_t src = (((size_t)s * 1024 + n) * 196 + min(r, 195)) * 256 + k0 + q;
          const int sz = (r < 196) ? 16 : 0;
          CP16(sb + OF_BH + r * 80 + q * 2, g_Kh + src, sz);
          CP16(sb + OF_BH + BHB + r * 80 + q * 2, g_Kl + src, sz);
        }
      } else {
        for (int idx = tid; idx < 112 * 4; idx += 224) {
          const int r = idx >> 2, q = (idx & 3) * 8;
          const int l = Lb + r;
          const size_t src = ((size_t)n * 196 + min(l, 195)) * 416 + k0 + q;
          const int sz = (l < 196) ? 16 : 0;
          CP16(sb + r * 80 + q * 2, g_Ph + src, sz);
          CP16(sb + 8960 + r * 80 + q * 2, g_Pl + src, sz);
        }
        for (int idx = tid; idx < 128 * 4; idx += 224) {
          const int r = idx >> 2, q = (idx & 3) * 8;
          const size_t src = ((size_t)n * 256 + c0 + r) * 416 + k0 + q;
          CP16(sb + OF_BH + r * 80 + q * 2, g_Vh + src, 16);
          CP16(sb + OF_BH + BHB + r * 80 + q * 2, g_Vl + src, 16);
        }
      }
      CPCOMMIT();
    };
    stage(0, 0);
#pragma unroll 1
    for (int ch = 0; ch < NCH; ch++) {
      const int buf = ch & 1;
      if (ch + 1 < NCH) { stage(ch + 1, buf ^ 1); CPWAIT1(); }
      else              { CPWAIT0(); }
      __syncthreads();
      domma(a_addr + (unsigned)buf * BUFSZ, b_addr + (unsigned)buf * BUFSZ);
      __syncthreads();
    }
  }

  // ---------------- epilogues ----------------
  if (MODE == 0) {
    const int p0 = blockIdx.x * 112, o0 = blockIdx.y * 128;
    const int b = p0 / hwin;
#pragma unroll
    for (int half = 0; half < 2; half++) {
      const int p = p0 + warp * 16 + qr + half * 8;
      const int pl = p - b * hwin;
      const int h = pl / 224, w = pl - (pl / 224) * 224;
      const int nn = (b << 8) + (h / 14) * 16 + (w / 14);
      const int l = (h % 14) * 14 + (w % 14);
      const size_t dst = ((size_t)nn * 196 + l) * 256;
#pragma unroll
      for (int nf = 0; nf < NF; nf++) {
        const int o = o0 + nf * 8 + kc2;
        unsigned uh, ul;
        split2(acc[nf][half * 2] + bias[o], acc[nf][half * 2 + 1] + bias[o + 1], uh, ul);
        *(unsigned*)&g_Qh[dst + o] = uh;
        *(unsigned*)&g_Ql[dst + o] = ul;
      }
    }
  } else if (MODE == 1) {
    const int p0 = blockIdx.x * 112, o0 = blockIdx.y * 128;
    float* outF = which ? g_VL : g_KL;
#pragma unroll
    for (int half = 0; half < 2; half++) {
      const int p = p0 + warp * 16 + qr + half * 8;
      float* dst = outF + (size_t)p * 256;
#pragma unroll
      for (int nf = 0; nf < NF; nf++) {
        const int o = o0 + nf * 8 + kc2;
        *(float2*)&dst[o] =
            make_float2(acc[nf][half * 2] + bias[o], acc[nf][half * 2 + 1] + bias[o + 1]);
      }
    }
  } else if (MODE == 2) {
    const int Lb = blockIdx.x * 112;
#pragma unroll
    for (int half = 0; half < 2; half++) {
      const int l = Lb + warp * 16 + qr + half * 8;
      const bool vl = (l < 196);
      float mx = -1e30f;
#pragma unroll
      for (int nf = 0; nf < NF; nf++) {
        if (nf * 8 + kc2 < 196)
          mx = fmaxf(mx, fmaxf(acc[nf][half * 2], acc[nf][half * 2 + 1]));
      }
      mx = fmaxf(mx, __shfl_xor_sync(0xffffffffu, mx, 1));
      mx = fmaxf(mx, __shfl_xor_sync(0xffffffffu, mx, 2));
      float sum = 0.f;
#pragma unroll
      for (int nf = 0; nf < NF; nf++) {
        if (nf * 8 + kc2 < 196) {
          float e0 = __expf(acc[nf][half * 2] - mx);
          float e1 = __expf(acc[nf][half * 2 + 1] - mx);
          acc[nf][half * 2] = e0; acc[nf][half * 2 + 1] = e1;
          sum += e0 + e1;
        }
      }
      sum += __shfl_xor_sync(0xffffffffu, sum, 1);
      sum += __shfl_xor_sync(0xffffffffu, sum, 2);
      const float inv = 1.f / sum;
      if (vl) {
        const size_t rb0 = ((size_t)n * 196 + l) * 416;
        const size_t rb  = rb0 + s * 196;
#pragma unroll
        for (int nf = 0; nf < NF; nf++) {
          const int m = nf * 8 + kc2;
          if (m < 196) {
            unsigned uh, ul;
            split2(acc[nf][half * 2] * inv, acc[nf][half * 2 + 1] * inv, uh, ul);
            *(unsigned*)&g_Ph[rb + m] = uh;
            *(unsigned*)&g_Pl[rb + m] = ul;
          }
        }
        if (s == 1) {   // zero the 392..415 pad once per row
#pragma unroll
          for (int i = 0; i < 3; i++) {
            *(unsigned*)&g_Ph[rb0 + 392 + i * 8 + kc2] = 0u;
            *(unsigned*)&g_Pl[rb0 + 392 + i * 8 + kc2] = 0u;
          }
        }
      }
    }
  } else {
    float* T = (float*)smem;   // [64][133]
    const int Lb = blockIdx.x * 112, c0 = blockIdx.y * 128;
    const int b = n >> 8, php = (n >> 4) & 15, pwp = n & 15;
#pragma unroll 1
    for (int pass = 0; pass < 2; pass++) {
      __syncthreads();
      if ((warp >> 2) == pass) {
        const int lr = warp * 16 + qr - pass * 64;
#pragma unroll
        for (int nf = 0; nf < NF; nf++) {
          const int c = nf * 8 + kc2;
          T[lr * 133 + c]           = acc[nf][0];
          T[lr * 133 + c + 1]       = acc[nf][1];
          T[(lr + 8) * 133 + c]     = acc[nf][2];
          T[(lr + 8) * 133 + c + 1] = acc[nf][3];
        }
      }
      __syncthreads();
      const int nrows = pass ? 48 : 64;
      for (int idx = tid; idx < 128 * 64; idx += 224) {
        const int c = idx >> 6, lr = idx & 63;
        const int l = Lb + pass * 64 + lr;
        if (lr < nrows && l < 196) {
          const int hh = php * 14 + l / 14, ww = pwp * 14 + l % 14;
          outp[(size_t)b * IMG_B + (size_t)(c0 + c) * HWF + hh * 224 + ww] = T[lr * 133 + c];
        }
      }
    }
  }
}

// ---------------- resize K: g_KL -> split g_Kh/g_Kl [s][n][m][c] ----------------
__global__ void resizeK_kernel(int hin, int s)
{
  const int r = blockIdx.x;                  // n*196 + m
  const int n = r / 196, m = r - n * 196;
  const int c4 = threadIdx.x * 4;            // 64 threads
  int i00, i01, i10, i11; float fh, fw;
  bilin(n, m, hin, i00, i01, i10, i11, fh, fw);
  const size_t bb = (size_t)(n >> 8) * hin * hin * 256;
  const float4 a = *(const float4*)&g_KL[bb + (size_t)i00 * 256 + c4];
  const float4 b = *(const float4*)&g_KL[bb + (size_t)i01 * 256 + c4];
  const float4 c = *(const float4*)&g_KL[bb + (size_t)i10 * 256 + c4];
  const float4 d = *(const float4*)&g_KL[bb + (size_t)i11 * 256 + c4];
  const float w00 = (1.f - fh) * (1.f - fw), w01 = (1.f - fh) * fw;
  const float w10 = fh * (1.f - fw), w11 = fh * fw;
  unsigned uh0, ul0, uh1, ul1;
  split2(w00 * a.x + w01 * b.x + w10 * c.x + w11 * d.x,
         w00 * a.y + w01 * b.y + w10 * c.y + w11 * d.y, uh0, ul0);
  split2(w00 * a.z + w01 * b.z + w10 * c.z + w11 * d.z,
         w00 * a.w + w01 * b.w + w10 * c.w + w11 * d.w, uh1, ul1);
  const size_t dst = (((size_t)s * 1024 + n) * 196 + m) * 256 + c4;
  *(uint2*)&g_Kh[dst] = make_uint2(uh0, uh1);
  *(uint2*)&g_Kl[dst] = make_uint2(ul0, ul1);
}

// ---------------- resize V + transpose: g_VL -> split g_Vh/g_Vl [n][c][416] ----------------
__global__ void resizeV_kernel(int hin, int s)
{
  __shared__ float sm[28 * 257];
  const int mt = blockIdx.x;      // 0..6 (7 = zero pad, s==1 launch only)
  const int n = blockIdx.y;
  const int c = threadIdx.x;      // 256
  if (mt == 7) {
    const size_t base = ((size_t)n * 256 + c) * 416 + 392;
#pragma unroll
    for (int i = 0; i < 12; i++) {
      *(unsigned*)&g_Vh[base + i * 2] = 0u;
      *(unsigned*)&g_Vl[base + i * 2] = 0u;
    }
    return;
  }
  const size_t bb = (size_t)(n >> 8) * hin * hin * 256;
#pragma unroll 1
  for (int li = 0; li < 28; li++) {
    int i00, i01, i10, i11; float fh, fw;
    bilin(n, mt * 28 + li, hin, i00, i01, i10, i11, fh, fw);
    const float v00 = g_VL[bb + (size_t)i00 * 256 + c], v01 = g_VL[bb + (size_t)i01 * 256 + c];
    const float v10 = g_VL[bb + (size_t)i10 * 256 + c], v11 = g_VL[bb + (size_t)i11 * 256 + c];
    sm[li * 257 + c] = (1.f - fh) * ((1.f - fw) * v00 + fw * v01)
                     + fh * ((1.f - fw) * v10 + fw * v11);
  }
  __syncthreads();
  for (int idx = c; idx < 14 * 256; idx += 256) {
    const int cc = idx / 14, li2 = (idx - cc * 14) * 2;
    unsigned uh, ul;
    split2(sm[li2 * 257 + cc], sm[(li2 + 1) * 257 + cc], uh, ul);
    const size_t dst = ((size_t)n * 256 + cc) * 416 + s * 196 + mt * 28 + li2;
    *(unsigned*)&g_Vh[dst] = uh;
    *(unsigned*)&g_Vl[dst] = ul;
  }
}

// ---------------- launcher ----------------
extern "C" void kernel_launch(void* const* d_in, const int* in_sizes, int n_in,
                              void* d_out, int out_size) {
  const float* x     = (const float*)d_in[0];
  const float* skip0 = (const float*)d_in[1];
  const float* skip1 = (const float*)d_in[2];
  const float* Wq    = (const float*)d_in[3];
  const float* bq    = (const float*)d_in[4];
  const float* Wk    = (const float*)d_in[5];
  const float* bk    = (const float*)d_in[6];
  const float* Wv    = (const float*)d_in[7];
  const float* bv    = (const float*)d_in[8];
  float* out = (float*)d_out;
  (void)in_sizes; (void)n_in; (void)out_size;

  static int inited = 0;
  if (!inited) {
    cudaFuncSetAttribute(mm_kernel<2>, cudaFuncAttributeMaxDynamicSharedMemorySize, 102400);
    cudaFuncSetAttribute(mm_kernel<3>, cudaFuncAttributeMaxDynamicSharedMemorySize, 76800);
    inited = 1;
  }

  mm_kernel<0><<<dim3(1792, 2), 224, 38400>>>(x, Wq, bq, nullptr, HWF, 0);

  for (int s = 0; s < 2; s++) {
    const float* skip = s ? skip1 : skip0;
    const int hin = s ? 56 : 112;
    const int hwin = hin * hin;
    const int mtiles = (4 * hwin) / 112;
    mm_kernel<1><<<dim3(mtiles, 2), 224, 38400>>>(skip, Wk, bk, nullptr, hwin, 0);
    mm_kernel<1><<<dim3(mtiles, 2), 224, 38400>>>(skip, Wv, bv, nullptr, hwin, 1);
    resizeK_kernel<<<200704, 64>>>(hin, s);
    resizeV_kernel<<<dim3(7 + s, 1024), 256>>>(hin, s);
  }

  // S + fused softmax (both skips in z), then fused AV -> out
  mm_kernel<2><<<dim3(2, 1, 2048), 224, 102400>>>(nullptr, nullptr, nullptr, nullptr, 0, 0);
  mm_kernel<3><<<dim3(2, 2, 1024), 224, 76800>>>(nullptr, nullptr, nullptr, out, 0, 0);
}

// round 7
// speedup vs baseline: 2.8833x; 1.1008x over previous
#include <cuda_runtime.h>
#include <cuda_bf16.h>
#include <cstdint>

#define HWF   50176
#define IMG_B 12845056

// ---------------- device scratch (split bf16 hi/lo) ----------------
__device__ unsigned short g_Qh[51380224],  g_Ql[51380224];    // [n][l][256]
__device__ unsigned short g_KLh[16056320], g_KLl[16056320];   // [b][pix(15680)][256]
__device__ unsigned short g_VLh[16056320], g_VLl[16056320];   // [b][pix][256]
__device__ unsigned short g_VLwh[33554432], g_VLwl[33554432]; // [n][c][128] window V
__device__ unsigned short g_Pwh[25690112],  g_Pwl[25690112];  // [n][l][128] window P

// ---------------- helpers ----------------
__device__ __forceinline__ void split_f32(float v, unsigned short& h, unsigned short& l) {
  __nv_bfloat16 bh = __float2bfloat16(v);
  h = __bfloat16_as_ushort(bh);
  l = __bfloat16_as_ushort(__float2bfloat16(v - __bfloat162float(bh)));
}
__device__ __forceinline__ void split2(float a, float b, unsigned& uh, unsigned& ul) {
  unsigned short h0, l0, h1, l1; split_f32(a, h0, l0); split_f32(b, h1, l1);
  uh = (unsigned)h0 | ((unsigned)h1 << 16);
  ul = (unsigned)l0 | ((unsigned)l1 << 16);
}
__device__ __forceinline__ void mma_bf16(float d[4], const unsigned a[4], const unsigned b[2]) {
  asm volatile("mma.sync.aligned.m16n8k16.row.col.f32.bf16.bf16.f32 "
               "{%0,%1,%2,%3}, {%4,%5,%6,%7}, {%8,%9}, {%0,%1,%2,%3};\n"
               : "+f"(d[0]), "+f"(d[1]), "+f"(d[2]), "+f"(d[3])
               : "r"(a[0]), "r"(a[1]), "r"(a[2]), "r"(a[3]), "r"(b[0]), "r"(b[1]));
}
#define LDSM4(r, addr) \
  asm volatile("ldmatrix.sync.aligned.m8n8.x4.shared.b16 {%0,%1,%2,%3},[%4];" \
               : "=r"(r[0]), "=r"(r[1]), "=r"(r[2]), "=r"(r[3]) : "r"(addr))
#define CP16(sm, gp, sz) \
  asm volatile("cp.async.cg.shared.global [%0],[%1],16,%2;\n" :: "r"(sm), "l"(gp), "r"(sz))
#define CPCOMMIT() asm volatile("cp.async.commit_group;\n" ::: "memory")
#define CPWAIT1()  asm volatile("cp.async.wait_group 1;\n" ::: "memory")
#define CPWAIT0()  asm volatile("cp.async.wait_group 0;\n" ::: "memory")

// window pixel for patch n, window slot j (0..127). -1 = zero pad.
// slots 0..80: s0 9x9 window; 88..112: s1 5x5 window.
__device__ __forceinline__ int win_pix(int n, int j) {
  const int ah = (n >> 4) & 15, aw = n & 15;
  if (j < 81) {
    const int jr = j / 9, jc = j - jr * 9;
    const int gr = min(max(7 * ah - 1 + jr, 0), 111);
    const int gc = min(max(7 * aw - 1 + jc, 0), 111);
    return gr * 112 + gc;
  }
  if (j >= 88 && j < 113) {
    const int jj = j - 88;
    const int jr = jj / 5, jc = jj - jr * 5;
    const int gr = min(max(((7 * ah - 1) >> 1) + jr, 0), 55);
    const int gc = min(max(((7 * aw - 1) >> 1) + jc, 0), 55);
    return 12544 + gr * 56 + gc;
  }
  return -1;
}

// ==================================================================
// mm_kernel MODE 0: Q proj  -> g_Qh/l [n][l][256]
//           MODE 1: low-res K/V proj -> g_KLh/l or g_VLh/l (split)
//           MODE 3: O = Plow · VLw^T (K=128) -> d_out unpatchified
// ==================================================================
template<int MODE>
__global__ void __launch_bounds__(224, 2) mm_kernel(
    const float* __restrict__ Ap, const float* __restrict__ Bp,
    const float* __restrict__ bias, float* __restrict__ outp,
    int hwin, int which, int offs)
{
  constexpr int NF    = 16;
  constexpr int NCH   = (MODE == 3) ? 4 : 8;
  constexpr int OF_BH = 17920;
  constexpr int BHB   = 128 * 80;
  constexpr int BUFSZ = OF_BH + 2 * BHB;   // 38400
  extern __shared__ __align__(16) unsigned char smem[];
  unsigned short* Ah = (unsigned short*)smem;
  unsigned short* Al = (unsigned short*)(smem + 8960);
  unsigned short* Bh = (unsigned short*)(smem + OF_BH);
  unsigned short* Bl = (unsigned short*)(smem + OF_BH + BHB);

  const int tid = threadIdx.x, warp = tid >> 5, lane = tid & 31;
  const int qr = lane >> 2, kc2 = (lane & 3) * 2;
  const int t8 = lane >> 3, l7 = lane & 7;
  const int n = blockIdx.z;

  const unsigned sbase  = (unsigned)__cvta_generic_to_shared(smem);
  const unsigned a_addr = sbase + ((warp * 16 + l7 + (t8 & 1) * 8) * 40 + (t8 >> 1) * 8) * 2;
  const unsigned b_addr = sbase + OF_BH + ((l7 + (t8 >> 1) * 8) * 40 + (t8 & 1) * 8) * 2;

  float acc[NF][4];
#pragma unroll
  for (int i = 0; i < NF; i++) { acc[i][0] = acc[i][1] = acc[i][2] = acc[i][3] = 0.f; }

  auto domma = [&](unsigned ao, unsigned bo) {
#pragma unroll
    for (int kk = 0; kk < 2; kk++) {
      unsigned ah[4], al[4];
      LDSM4(ah, ao + kk * 32);
      LDSM4(al, ao + 8960 + kk * 32);
#pragma unroll
      for (int nf = 0; nf < NF; nf += 2) {
        unsigned bh[4], bl4[4];
        LDSM4(bh,  bo + nf * 640 + kk * 32);
        LDSM4(bl4, bo + BHB + nf * 640 + kk * 32);
        mma_bf16(acc[nf], ah, bh);      mma_bf16(acc[nf + 1], ah, bh + 2);
        mma_bf16(acc[nf], al, bh);      mma_bf16(acc[nf + 1], al, bh + 2);
        mma_bf16(acc[nf], ah, bl4);     mma_bf16(acc[nf + 1], ah, bl4 + 2);
      }
    }
  };

  if (MODE <= 1) {
#pragma unroll 1
    for (int ch = 0; ch < NCH; ch++) {
      const int k0 = ch * 32;
      const int p0 = blockIdx.x * 112;
      const int b = p0 / hwin;
      const float* xb = Ap + (size_t)b * 256 * hwin + (p0 - b * hwin);
      for (int idx = tid; idx < 32 * 112; idx += 224) {
        const int kk = idx / 112, p = idx - kk * 112;
        unsigned short h, l; split_f32(xb[(size_t)(k0 + kk) * hwin + p], h, l);
        Ah[p * 40 + kk] = h; Al[p * 40 + kk] = l;
      }
      const int o0 = blockIdx.y * 128;
      for (int idx = tid; idx < 128 * 16; idx += 224) {
        const int r = idx >> 4, cc = (idx & 15) * 2;
        float2 v = *(const float2*)&Bp[(o0 + r) * 256 + k0 + cc];
        unsigned uh, ul; split2(v.x, v.y, uh, ul);
        *(unsigned*)&Bh[r * 40 + cc] = uh;
        *(unsigned*)&Bl[r * 40 + cc] = ul;
      }
      __syncthreads();
      domma(a_addr, b_addr);
      __syncthreads();
    }
  } else {
    const int Lb = blockIdx.x * 112;
    const int c0 = blockIdx.y * 128;
    auto stage = [&](int ch, int buf) {
      const unsigned sb = sbase + (unsigned)buf * BUFSZ;
      const int k0 = ch * 32;
      for (int idx = tid; idx < 112 * 4; idx += 224) {
        const int r = idx >> 2, q = (idx & 3) * 8;
        const int l = Lb + r;
        const size_t src = ((size_t)n * 196 + min(l, 195)) * 128 + k0 + q;
        const int sz = (l < 196) ? 16 : 0;
        CP16(sb + r * 80 + q * 2, g_Pwh + src, sz);
        CP16(sb + 8960 + r * 80 + q * 2, g_Pwl + src, sz);
      }
      for (int idx = tid; idx < 128 * 4; idx += 224) {
        const int r = idx >> 2, q = (idx & 3) * 8;
        const size_t src = ((size_t)n * 256 + c0 + r) * 128 + k0 + q;
        CP16(sb + OF_BH + r * 80 + q * 2, g_VLwh + src, 16);
        CP16(sb + OF_BH + BHB + r * 80 + q * 2, g_VLwl + src, 16);
      }
      CPCOMMIT();
    };
    stage(0, 0);
#pragma unroll 1
    for (int ch = 0; ch < NCH; ch++) {
      const int buf = ch & 1;
      if (ch + 1 < NCH) { stage(ch + 1, buf ^ 1); CPWAIT1(); }
      else              { CPWAIT0(); }
      __syncthreads();
      domma(a_addr + (unsigned)buf * BUFSZ, b_addr + (unsigned)buf * BUFSZ);
      __syncthreads();
    }
  }

  // ---------------- epilogues ----------------
  if (MODE == 0) {
    const int p0 = blockIdx.x * 112, o0 = blockIdx.y * 128;
    const int b = p0 / hwin;
#pragma unroll
    for (int half = 0; half < 2; half++) {
      const int p = p0 + warp * 16 + qr + half * 8;
      const int pl = p - b * hwin;
      const int h = pl / 224, w = pl - (pl / 224) * 224;
      const int nn = (b << 8) + (h / 14) * 16 + (w / 14);
      const int l = (h % 14) * 14 + (w % 14);
      const size_t dst = ((size_t)nn * 196 + l) * 256;
#pragma unroll
      for (int nf = 0; nf < NF; nf++) {
        const int o = o0 + nf * 8 + kc2;
        unsigned uh, ul;
        split2(acc[nf][half * 2] + bias[o], acc[nf][half * 2 + 1] + bias[o + 1], uh, ul);
        *(unsigned*)&g_Qh[dst + o] = uh;
        *(unsigned*)&g_Ql[dst + o] = ul;
      }
    }
  } else if (MODE == 1) {
    const int p0 = blockIdx.x * 112, o0 = blockIdx.y * 128;
    const int b = p0 / hwin;
    unsigned short* dh = which ? g_VLh : g_KLh;
    unsigned short* dl = which ? g_VLl : g_KLl;
#pragma unroll
    for (int half = 0; half < 2; half++) {
      const int p = p0 + warp * 16 + qr + half * 8;
      const int pl = p - b * hwin;
      const size_t dst = ((size_t)b * 15680 + offs + pl) * 256;
#pragma unroll
      for (int nf = 0; nf < NF; nf++) {
        const int o = o0 + nf * 8 + kc2;
        unsigned uh, ul;
        split2(acc[nf][half * 2] + bias[o], acc[nf][half * 2 + 1] + bias[o + 1], uh, ul);
        *(unsigned*)&dh[dst + o] = uh;
        *(unsigned*)&dl[dst + o] = ul;
      }
    }
  } else {
    float* T = (float*)smem;   // [64][133]
    const int Lb = blockIdx.x * 112, c0 = blockIdx.y * 128;
    const int b = n >> 8, php = (n >> 4) & 15, pwp = n & 15;
#pragma unroll 1
    for (int pass = 0; pass < 2; pass++) {
      __syncthreads();
      if ((warp >> 2) == pass) {
        const int lr = warp * 16 + qr - pass * 64;
#pragma unroll
        for (int nf = 0; nf < NF; nf++) {
          const int c = nf * 8 + kc2;
          T[lr * 133 + c]           = acc[nf][0];
          T[lr * 133 + c + 1]       = acc[nf][1];
          T[(lr + 8) * 133 + c]     = acc[nf][2];
          T[(lr + 8) * 133 + c + 1] = acc[nf][3];
        }
      }
      __syncthreads();
      const int nrows = pass ? 48 : 64;
      for (int idx = tid; idx < 128 * 64; idx += 224) {
        const int c = idx >> 6, lr = idx & 63;
        const int l = Lb + pass * 64 + lr;
        if (lr < nrows && l < 196) {
          const int hh = php * 14 + l / 14, ww = pwp * 14 + l % 14;
          outp[(size_t)b * IMG_B + (size_t)(c0 + c) * HWF + hh * 224 + ww] = T[lr * 133 + c];
        }
      }
    }
  }
}

// ---------------- S_low + softmax expansion + P fold ----------------
template<int WS>
__device__ __forceinline__ float pass_max(
    const float* SLr, const int* JRp, const float* FRp, const float* FCs,
    const int* cs, int mi0)
{
  float mx = -1e30f;
#pragma unroll 1
  for (int mi = mi0; mi < mi0 + 7; mi++) {
    const int jr = JRp[mi]; const float fr = FRp[mi];
    float H[WS];
#pragma unroll
    for (int jc = 0; jc < WS; jc++)
      H[jc] = (1.f - fr) * SLr[jr * WS + jc] + fr * SLr[(jr + 1) * WS + jc];
#pragma unroll
    for (int jc = 0; jc + 1 < WS; jc++) {
      for (int mj = cs[jc]; mj < cs[jc + 1]; mj++) {
        const float fc = FCs[mj];
        mx = fmaxf(mx, (1.f - fc) * H[jc] + fc * H[jc + 1]);
      }
    }
  }
  return mx;
}
template<int WS>
__device__ __forceinline__ float pass_fold(
    const float* SLr, float* PLr, const int* JRp, const float* FRp, const float* FCs,
    const int* cs, int mi0, float mx)
{
  float sum = 0.f;
#pragma unroll 1
  for (int mi = mi0; mi < mi0 + 7; mi++) {
    const int jr = JRp[mi]; const float fr = FRp[mi];
    float H[WS], T[WS];
#pragma unroll
    for (int jc = 0; jc < WS; jc++) {
      H[jc] = (1.f - fr) * SLr[jr * WS + jc] + fr * SLr[(jr + 1) * WS + jc];
      T[jc] = 0.f;
    }
#pragma unroll
    for (int jc = 0; jc + 1 < WS; jc++) {
      for (int mj = cs[jc]; mj < cs[jc + 1]; mj++) {
        const float fc = FCs[mj];
        const float e = __expf((1.f - fc) * H[jc] + fc * H[jc + 1] - mx);
        sum += e;
        T[jc]     += e * (1.f - fc);
        T[jc + 1] += e * fc;
      }
    }
#pragma unroll
    for (int jc = 0; jc < WS; jc++) {
      atomicAdd(&PLr[jr * WS + jc],       (1.f - fr) * T[jc]);
      atomicAdd(&PLr[(jr + 1) * WS + jc], fr * T[jc]);
    }
  }
  return sum;
}

__global__ void __launch_bounds__(224, 1) attn_s_kernel()
{
  // smem: mainloop bufs [0,74240); epi: Slow[112][124] @0, Plow[112][128] @55552;
  // JR@112896 FR@113008 JC@113120 FC@113232 tbl@113344 CS@113824
  extern __shared__ __align__(16) unsigned char smem[];
  const unsigned sbase = (unsigned)__cvta_generic_to_shared(smem);
  int*   JR  = (int*)(smem + 112896);
  float* FR  = (float*)(smem + 113008);
  int*   JC  = (int*)(smem + 113120);
  float* FC  = (float*)(smem + 113232);
  int*   tbl = (int*)(smem + 113344);
  int*   CS  = (int*)(smem + 113824);

  const int tid = threadIdx.x, warp = tid >> 5, lane = tid & 31;
  const int qr = lane >> 2, kc2 = (lane & 3) * 2;
  const int t8 = lane >> 3, l7 = lane & 7;
  const int n = blockIdx.z, b = n >> 8;
  const int Lb = blockIdx.x * 112;
  const int ah = (n >> 4) & 15, aw = n & 15;

  for (int j = tid; j < 120; j += 224) tbl[j] = win_pix(n, j);
  if (tid < 28) {
    const int s = tid / 14, u = tid - s * 14;
    const float sc = s ? 0.25f : 0.5f;
    const int baseh = s ? ((7 * ah - 1) >> 1) : (7 * ah - 1);
    const int basew = s ? ((7 * aw - 1) >> 1) : (7 * aw - 1);
    float sh = (14 * ah + u + 0.5f) * sc - 0.5f;
    int ih = (int)floorf(sh);
    JR[tid] = ih - baseh; FR[tid] = sh - (float)ih;
    sh = (14 * aw + u + 0.5f) * sc - 0.5f;
    ih = (int)floorf(sh);
    JC[tid] = ih - basew; FC[tid] = sh - (float)ih;
  }
  __syncthreads();
  if (tid < 2) {
    const int WS = tid ? 5 : 9;
    int* cs = CS + tid * 10;
    for (int k = 0; k < WS; k++) {
      int cnt = 0;
      for (int u = 0; u < 14; u++) if (JC[tid * 14 + u] < k) cnt++;
      cs[k] = cnt;
    }
  }

  const unsigned a_addr = sbase + ((warp * 16 + l7 + (t8 & 1) * 8) * 40 + (t8 >> 1) * 8) * 2;
  const unsigned b_addr = sbase + 17920 + ((l7 + (t8 >> 1) * 8) * 40 + (t8 & 1) * 8) * 2;
  constexpr int NF = 15, BHB = 9600, BUFSZ = 37120;

  float acc[NF][4];
#pragma unroll
  for (int i = 0; i < NF; i++) { acc[i][0] = acc[i][1] = acc[i][2] = acc[i][3] = 0.f; }

  auto stage = [&](int ch, int buf) {
    const unsigned sb = sbase + (unsigned)buf * BUFSZ;
    const int k0 = ch * 32;
    for (int idx = tid; idx < 112 * 4; idx += 224) {
      const int r = idx >> 2, q = (idx & 3) * 8;
      const int l = Lb + r;
      const size_t src = ((size_t)n * 196 + min(l, 195)) * 256 + k0 + q;
      const int sz = (l < 196) ? 16 : 0;
      CP16(sb + r * 80 + q * 2, g_Qh + src, sz);
      CP16(sb + 8960 + r * 80 + q * 2, g_Ql + src, sz);
    }
    for (int idx = tid; idx < 120 * 4; idx += 224) {
      const int r = idx >> 2, q = (idx & 3) * 8;
      const int pix = tbl[r];
      const size_t src = ((size_t)b * 15680 + max(pix, 0)) * 256 + k0 + q;
      const int sz = (pix >= 0) ? 16 : 0;
      CP16(sb + 17920 + r * 80 + q * 2, g_KLh + src, sz);
      CP16(sb + 27520 + r * 80 + q * 2, g_KLl + src, sz);
    }
    CPCOMMIT();
  };

  stage(0, 0);
#pragma unroll 1
  for (int ch = 0; ch < 8; ch++) {
    const int buf = ch & 1;
    if (ch + 1 < 8) { stage(ch + 1, buf ^ 1); CPWAIT1(); }
    else            { CPWAIT0(); }
    __syncthreads();
    const unsigned ao = a_addr + (unsigned)buf * BUFSZ;
    const unsigned bo = b_addr + (unsigned)buf * BUFSZ;
#pragma unroll
    for (int kk = 0; kk < 2; kk++) {
      unsigned ahf[4], alf[4];
      LDSM4(ahf, ao + kk * 32);
      LDSM4(alf, ao + 8960 + kk * 32);
#pragma unroll
      for (int nf = 0; nf + 1 < NF; nf += 2) {
        unsigned bh[4], bl4[4];
        LDSM4(bh,  bo + nf * 640 + kk * 32);
        LDSM4(bl4, bo + BHB + nf * 640 + kk * 32);
        mma_bf16(acc[nf], ahf, bh);      mma_bf16(acc[nf + 1], ahf, bh + 2);
        mma_bf16(acc[nf], alf, bh);      mma_bf16(acc[nf + 1], alf, bh + 2);
        mma_bf16(acc[nf], ahf, bl4);     mma_bf16(acc[nf + 1], ahf, bl4 + 2);
      }
      { // tail frag nf=14
        unsigned bh[4], bl4[4];
        LDSM4(bh,  bo + 14 * 640 + kk * 32);
        LDSM4(bl4, bo + BHB + 14 * 640 + kk * 32);
        mma_bf16(acc[14], ahf, bh);
        mma_bf16(acc[14], alf, bh);
        mma_bf16(acc[14], ahf, bl4);
      }
    }
    __syncthreads();
  }

  // ---- epilogue: dump S_low, softmax-expand, fold to Plow, write split ----
  float* SL = (float*)smem;              // [112][124]
  float* PL = (float*)(smem + 55552);    // [112][128]
  {
    const int row = warp * 16 + qr;
#pragma unroll
    for (int nf = 0; nf < NF; nf++) {
      const int c = nf * 8 + kc2;
      SL[row * 124 + c]           = acc[nf][0];
      SL[row * 124 + c + 1]       = acc[nf][1];
      SL[(row + 8) * 124 + c]     = acc[nf][2];
      SL[(row + 8) * 124 + c + 1] = acc[nf][3];
    }
  }
  for (int idx = tid; idx < 112 * 128; idx += 224) ((float*)PL)[idx] = 0.f;
  __syncthreads();

  const int r = tid >> 1, hf = tid & 1;
  const int l = Lb + r;
  const int mi0 = hf * 7;
  float invs[2] = {0.f, 0.f};
  if (l < 196) {
    const float* SLr = SL + r * 124;
    float* PLr = PL + r * 128;
    { // skip 0: WS=9, cols 0..80
      float mx = pass_max<9>(SLr, JR, FR, FC, CS, mi0);
      mx = fmaxf(mx, __shfl_xor_sync(0xffffffffu, mx, 1));
      float sum = pass_fold<9>(SLr, PLr, JR, FR, FC, CS, mi0, mx);
      sum += __shfl_xor_sync(0xffffffffu, sum, 1);
      invs[0] = 1.f / sum;
    }
    { // skip 1: WS=5, cols 88..112
      float mx = pass_max<5>(SLr + 88, JR + 14, FR + 14, FC + 14, CS + 10, mi0);
      mx = fmaxf(mx, __shfl_xor_sync(0xffffffffu, mx, 1));
      float sum = pass_fold<5>(SLr + 88, PLr + 88, JR + 14, FR + 14, FC + 14, CS + 10, mi0, mx);
      sum += __shfl_xor_sync(0xffffffffu, sum, 1);
      invs[1] = 1.f / sum;
    }
  } else {
    __shfl_xor_sync(0xffffffffu, 0.f, 1); __shfl_xor_sync(0xffffffffu, 0.f, 1);
    __shfl_xor_sync(0xffffffffu, 0.f, 1); __shfl_xor_sync(0xffffffffu, 0.f, 1);
  }
  __syncthreads();

  if (l < 196) {
    const size_t ob = ((size_t)n * 196 + l) * 128;
    const float* PLr = PL + r * 128;
#pragma unroll
    for (int c = 0; c < 64; c += 2) {
      const int cc = hf * 64 + c;
      const float scl = (cc < 88) ? invs[0] : invs[1];
      unsigned uh, ul;
      split2(PLr[cc] * scl, PLr[cc + 1] * scl, uh, ul);
      *(unsigned*)&g_Pwh[ob + cc] = uh;
      *(unsigned*)&g_Pwl[ob + cc] = ul;
    }
  }
}

// ---------------- gather V windows: g_VLh/l -> g_VLwh/l [n][c][128] ----------------
__global__ void __launch_bounds__(256) gatherV_kernel()
{
  const int n = blockIdx.x, c = threadIdx.x;
  const size_t bb = (size_t)(n >> 8) * 15680;
  const size_t ob = ((size_t)n * 256 + c) * 128;
#pragma unroll 1
  for (int q = 0; q < 16; q++) {
    unsigned hv[4], lv[4];
#pragma unroll
    for (int jj = 0; jj < 8; jj += 2) {
      const int j0 = q * 8 + jj;
      const int p0 = win_pix(n, j0), p1 = win_pix(n, j0 + 1);
      unsigned short h0 = (p0 < 0) ? 0 : g_VLh[(bb + p0) * 256 + c];
      unsigned short h1 = (p1 < 0) ? 0 : g_VLh[(bb + p1) * 256 + c];
      unsigned short l0 = (p0 < 0) ? 0 : g_VLl[(bb + p0) * 256 + c];
      unsigned short l1 = (p1 < 0) ? 0 : g_VLl[(bb + p1) * 256 + c];
      hv[jj >> 1] = (unsigned)h0 | ((unsigned)h1 << 16);
      lv[jj >> 1] = (unsigned)l0 | ((unsigned)l1 << 16);
    }
    *(uint4*)&g_VLwh[ob + q * 8] = make_uint4(hv[0], hv[1], hv[2], hv[3]);
    *(uint4*)&g_VLwl[ob + q * 8] = make_uint4(lv[0], lv[1], lv[2], lv[3]);
  }
}

// ---------------- launcher ----------------
extern "C" void kernel_launch(void* const* d_in, const int* in_sizes, int n_in,
                              void* d_out, int out_size) {
  const float* x     = (const float*)d_in[0];
  const float* skip0 = (const float*)d_in[1];
  const float* skip1 = (const float*)d_in[2];
  const float* Wq    = (const float*)d_in[3];
  const float* bq    = (const float*)d_in[4];
  const float* Wk    = (const float*)d_in[5];
  const float* bk    = (const float*)d_in[6];
  const float* Wv    = (const float*)d_in[7];
  const float* bv    = (const float*)d_in[8];
  float* out = (float*)d_out;
  (void)in_sizes; (void)n_in; (void)out_size;

  cudaFuncSetAttribute(attn_s_kernel, cudaFuncAttributeMaxDynamicSharedMemorySize, 114176);
  cudaFuncSetAttribute(mm_kernel<3>, cudaFuncAttributeMaxDynamicSharedMemorySize, 76800);

  // Q projection -> split [n][l][256]
  mm_kernel<0><<<dim3(1792, 2), 224, 38400>>>(x, Wq, bq, nullptr, HWF, 0, 0);

  for (int s = 0; s < 2; s++) {
    const float* skip = s ? skip1 : skip0;
    const int hwin = s ? 3136 : 12544;
    const int offs = s ? 12544 : 0;
    const int mtiles = (4 * hwin) / 112;
    mm_kernel<1><<<dim3(mtiles, 2), 224, 38400>>>(skip, Wk, bk, nullptr, hwin, 0, offs);
    mm_kernel<1><<<dim3(mtiles, 2), 224, 38400>>>(skip, Wv, bv, nullptr, hwin, 1, offs);
  }

  gatherV_kernel<<<1024, 256>>>();

  // S_low + softmax + fold -> Plow
  attn_s_kernel<<<dim3(2, 1, 1024), 224, 114176>>>();

  // O = Plow · VLw^T -> out (unpatchified)
  mm_kernel<3><<<dim3(2, 2, 1024), 224, 76800>>>(nullptr, nullptr, nullptr, out, 0, 0, 0);
}